// round 5
// baseline (speedup 1.0000x reference)
#include <cuda_runtime.h>
#include <math.h>
#include <stdint.h>

// Problem constants
#define Bb   2
#define Ss   2048
#define Ee   768
#define Hh   12
#define Dd   64
#define FFf  3072
#define Mrows (Bb*Ss)   // 4096

// ---------------------------------------------------------------------------
// Scratch (static device globals; no runtime allocation allowed)
// ---------------------------------------------------------------------------
__device__ float g_xn [Mrows*Ee];
__device__ float g_q  [Mrows*Ee];
__device__ float g_k  [Mrows*Ee];
__device__ float g_v  [Mrows*Ee];
__device__ float g_at [Mrows*Ee];
__device__ float g_res[Mrows*Ee];
__device__ float g_y  [Mrows*Ee];
__device__ float g_h  [Mrows*FFf];
// RN-rounded tf32 weight copies
__device__ float g_wq[Ee*Ee];
__device__ float g_wk[Ee*Ee];
__device__ float g_wv[Ee*Ee];
__device__ float g_wo[Ee*Ee];
__device__ float g_w1[FFf*Ee];
__device__ float g_w2[Ee*FFf];

// ---------------------------------------------------------------------------
// Helpers
// ---------------------------------------------------------------------------
__device__ __forceinline__ uint32_t smem_u32(const void* p) {
    uint32_t a;
    asm("{ .reg .u64 t; cvta.to.shared.u64 t, %1; cvt.u32.u64 %0, t; }"
        : "=r"(a) : "l"(p));
    return a;
}
__device__ __forceinline__ void cp16(uint32_t dst, const void* src) {
    asm volatile("cp.async.cg.shared.global [%0], [%1], 16;"
                 :: "r"(dst), "l"(src));
}
#define CP_COMMIT() asm volatile("cp.async.commit_group;" ::: "memory")
#define CP_WAIT(n)  asm volatile("cp.async.wait_group %0;" :: "n"(n) : "memory")

// round-to-nearest tf32 (kills truncation bias in mma operands)
__device__ __forceinline__ float rna(float x) {
    uint32_t u;
    asm("cvt.rna.tf32.f32 %0, %1;" : "=r"(u) : "f"(x));
    return __uint_as_float(u);
}

// D += A(16x8,row) * B(8x8,col as B^T rows)  tf32 inputs (raw fp32 bits)
__device__ __forceinline__ void mma_tf32(float* c, const uint32_t* a,
                                         uint32_t b0, uint32_t b1) {
    asm volatile(
        "mma.sync.aligned.m16n8k8.row.col.f32.tf32.tf32.f32 "
        "{%0,%1,%2,%3}, {%4,%5,%6,%7}, {%8,%9}, {%0,%1,%2,%3};"
        : "+f"(c[0]), "+f"(c[1]), "+f"(c[2]), "+f"(c[3])
        : "r"(a[0]), "r"(a[1]), "r"(a[2]), "r"(a[3]), "r"(b0), "r"(b1));
}

// ---------------------------------------------------------------------------
// Weight rounding: dst = rna_tf32(src), vectorized
// ---------------------------------------------------------------------------
__global__ void round_kernel(const float* __restrict__ s,
                             float* __restrict__ d, int n)
{
    const int i = (blockIdx.x * blockDim.x + threadIdx.x) * 4;
    if (i < n) {
        float4 v = *(const float4*)(s + i);
        v.x = rna(v.x); v.y = rna(v.y); v.z = rna(v.z); v.w = rna(v.w);
        *(float4*)(d + i) = v;
    }
}

// ---------------------------------------------------------------------------
// LayerNorm (outputs rounded to tf32-RN: they only feed GEMM A operands)
// ---------------------------------------------------------------------------
__global__ void ln_kernel(const float* __restrict__ X,
                          const float* __restrict__ gamma,
                          const float* __restrict__ beta,
                          float* __restrict__ Y)
{
    const int row = blockIdx.x;
    const float* x = X + (size_t)row * Ee;
    float*       y = Y + (size_t)row * Ee;
    const int t = threadIdx.x;

    float v0 = x[t], v1 = x[t + 256], v2 = x[t + 512];
    float s  = v0 + v1 + v2;

    __shared__ float red[8];
    #pragma unroll
    for (int off = 16; off; off >>= 1) s += __shfl_xor_sync(0xffffffffu, s, off);
    if ((t & 31) == 0) red[t >> 5] = s;
    __syncthreads();
    if (t < 8) {
        float r = red[t];
        #pragma unroll
        for (int off = 4; off; off >>= 1) r += __shfl_xor_sync(0xffu, r, off);
        if (t == 0) red[0] = r;
    }
    __syncthreads();
    const float mu = red[0] * (1.0f / Ee);
    __syncthreads();

    float d0 = v0 - mu, d1 = v1 - mu, d2 = v2 - mu;
    float q  = d0*d0 + d1*d1 + d2*d2;
    #pragma unroll
    for (int off = 16; off; off >>= 1) q += __shfl_xor_sync(0xffffffffu, q, off);
    if ((t & 31) == 0) red[t >> 5] = q;
    __syncthreads();
    if (t < 8) {
        float r = red[t];
        #pragma unroll
        for (int off = 4; off; off >>= 1) r += __shfl_xor_sync(0xffu, r, off);
        if (t == 0) red[0] = r;
    }
    __syncthreads();
    const float inv = rsqrtf(red[0] * (1.0f / Ee) + 1e-5f);

    y[t      ] = rna(d0 * inv * gamma[t      ] + beta[t      ]);
    y[t + 256] = rna(d1 * inv * gamma[t + 256] + beta[t + 256]);
    y[t + 512] = rna(d2 * inv * gamma[t + 512] + beta[t + 512]);
}

// ---------------------------------------------------------------------------
// tf32 tensor-core GEMM: C[M,N] = A[M,K] * B[N,K]^T (+ epilogue)
// CTA 128x128, 8 warps (4x2), warp tile 32x64, m16n8k8 HMMA.
// 3-stage cp.async pipeline (K-chunk 64) + register-double-buffered fragments.
// ---------------------------------------------------------------------------
enum { EPI_NONE = 0, EPI_BIAS = 1, EPI_BIAS_GELU = 2, EPI_BIAS_RES = 3 };

#define PITCH   68                       // floats per smem row (64 + 4 pad)
#define TILEF   (128*PITCH)              // floats per matrix per stage
#define STAGEB  (2*TILEF*4)              // bytes per stage (A+B)
#define NSTAGE  3
#define SMEMB   (NSTAGE*STAGEB)          // 208896 bytes

template <int EPI, int NQKV, bool ROUT>
__global__ __launch_bounds__(256, 1)
void gemm_mma(const float* __restrict__ A,
              const float* __restrict__ Bq, const float* __restrict__ Bk,
              const float* __restrict__ Bv,
              const float* __restrict__ bias, const float* __restrict__ R,
              float* __restrict__ Cq, float* __restrict__ Ck,
              float* __restrict__ Cv,
              int M, int N, int K)
{
    const float* Bm = Bq;
    float*       C  = Cq;
    if (NQKV == 3) {
        if (blockIdx.z == 1)      { Bm = Bk; C = Ck; }
        else if (blockIdx.z == 2) { Bm = Bv; C = Cv; }
    }

    extern __shared__ float sm[];

    const int t    = threadIdx.x;
    const int lane = t & 31;
    const int wid  = t >> 5;
    const int wr   = wid & 3;            // warp row (m)
    const int wc   = wid >> 2;           // warp col (n)
    const int mr   = wr * 32;
    const int nc0  = wc * 64;
    const int g    = lane >> 2;          // group id 0..7
    const int tg   = lane & 3;           // thread-in-group 0..3
    const int r0   = t >> 4;             // 0..15
    const int c4   = t & 15;             // float4 col within K-chunk

    const int bm = blockIdx.y * 128;
    const int bn = blockIdx.x * 128;

    float c[2][8][4];
    #pragma unroll
    for (int mt = 0; mt < 2; mt++)
        #pragma unroll
        for (int nt = 0; nt < 8; nt++)
            #pragma unroll
            for (int i = 0; i < 4; i++) c[mt][nt][i] = 0.f;

    const uint32_t sBase = smem_u32(sm);

    auto issue = [&](int ci) {
        const int st = ci % NSTAGE;
        const int k0 = ci << 6;
        const uint32_t dA = sBase + (uint32_t)st * STAGEB;
        const uint32_t dB = dA + TILEF * 4;
        #pragma unroll
        for (int p = 0; p < 8; p++) {
            const int row = p * 16 + r0;
            const uint32_t so = (uint32_t)(row * PITCH + c4 * 4) * 4;
            cp16(dA + so, A  + (size_t)(bm + row) * K + k0 + c4 * 4);
            cp16(dB + so, Bm + (size_t)(bn + row) * K + k0 + c4 * 4);
        }
        CP_COMMIT();
    };

    const int nchunk = K >> 6;
    issue(0);
    issue(1);

    #pragma unroll 1
    for (int ci = 0; ci < nchunk; ci++) {
        if (ci + 2 < nchunk) { issue(ci + 2); CP_WAIT(2); }
        else if (ci + 1 < nchunk) { CP_WAIT(1); }
        else { CP_WAIT(0); }
        __syncthreads();

        const float* sa = sm + (ci % NSTAGE) * (2 * TILEF);
        const float* sb = sa + TILEF;

        uint32_t afr[2][8], bfr[2][16];

        auto ldfr = [&](int kk, uint32_t* af, uint32_t* bf) {
            const int kb = kk * 8;
            #pragma unroll
            for (int mt = 0; mt < 2; mt++) {
                const float* p0 = sa + (mr + mt * 16 + g) * PITCH + kb + tg;
                const float* p1 = p0 + 8 * PITCH;
                af[mt*4+0] = __float_as_uint(p0[0]);
                af[mt*4+1] = __float_as_uint(p1[0]);
                af[mt*4+2] = __float_as_uint(p0[4]);
                af[mt*4+3] = __float_as_uint(p1[4]);
            }
            #pragma unroll
            for (int nt = 0; nt < 8; nt++) {
                const float* q0 = sb + (nc0 + nt * 8 + g) * PITCH + kb + tg;
                bf[nt*2+0] = __float_as_uint(q0[0]);
                bf[nt*2+1] = __float_as_uint(q0[4]);
            }
        };

        ldfr(0, afr[0], bfr[0]);
        #pragma unroll
        for (int kk = 0; kk < 8; kk++) {
            const int cur = kk & 1;
            if (kk < 7) ldfr(kk + 1, afr[cur ^ 1], bfr[cur ^ 1]);
            #pragma unroll
            for (int nt = 0; nt < 8; nt++) {
                mma_tf32(c[0][nt], &afr[cur][0], bfr[cur][nt*2], bfr[cur][nt*2+1]);
                mma_tf32(c[1][nt], &afr[cur][4], bfr[cur][nt*2], bfr[cur][nt*2+1]);
            }
        }
        __syncthreads();
    }

    // Epilogue: rows bm+mr+mt*16+{g,g+8}; cols bn+nc0+nt*8+2*tg+{0,1}
    #pragma unroll
    for (int mt = 0; mt < 2; mt++) {
        #pragma unroll
        for (int half = 0; half < 2; half++) {
            const int row = bm + mr + mt * 16 + g + half * 8;
            #pragma unroll
            for (int nt = 0; nt < 8; nt++) {
                const int col = bn + nc0 + nt * 8 + 2 * tg;
                float2 v = make_float2(c[mt][nt][half * 2 + 0],
                                       c[mt][nt][half * 2 + 1]);
                if (EPI >= EPI_BIAS) {
                    float2 bb = *(const float2*)(bias + col);
                    v.x += bb.x; v.y += bb.y;
                }
                if (EPI == EPI_BIAS_GELU) {
                    v.x = 0.5f * v.x * (1.0f + erff(v.x * 0.70710678118654752f));
                    v.y = 0.5f * v.y * (1.0f + erff(v.y * 0.70710678118654752f));
                }
                if (EPI == EPI_BIAS_RES) {
                    float2 rr = *(const float2*)(R + (size_t)row * N + col);
                    v.x += rr.x; v.y += rr.y;
                }
                if (ROUT) { v.x = rna(v.x); v.y = rna(v.y); }
                *(float2*)(C + (size_t)row * N + col) = v;
            }
        }
    }
}

// ---------------------------------------------------------------------------
// Flash attention (fp32, causal, online softmax); output rounded (feeds O-proj)
// ---------------------------------------------------------------------------
#define LDA 68
__global__ __launch_bounds__(256, 2)
void flash_kernel(const float* __restrict__ Qg, const float* __restrict__ Kg,
                  const float* __restrict__ Vg, float* __restrict__ Og)
{
    extern __shared__ float sm[];
    float* Qs = sm;
    float* Kt = sm + 64 * LDA;
    float* Vs = sm + 2 * 64 * LDA;
    float* Ps = sm + 3 * 64 * LDA;

    const int qt = blockIdx.x, h = blockIdx.y, b = blockIdx.z;
    const int q0 = qt * 64;
    const int t  = threadIdx.x;
    const int ty = t >> 4, tx = t & 15;
    const int lr = t >> 2, lq = t & 3;
    const size_t base = (size_t)b * Ss * Ee + h * Dd;

    {
        const float* qp = Qg + base + (size_t)(q0 + lr) * Ee;
        #pragma unroll
        for (int c = 0; c < 4; c++) {
            const int col = (c * 4 + lq) * 4;
            *(float4*)&Qs[lr * LDA + col] = *(const float4*)(qp + col);
        }
    }

    float m[4], l[4], o[4][4];
    #pragma unroll
    for (int i = 0; i < 4; i++) {
        m[i] = -INFINITY; l[i] = 0.f;
        #pragma unroll
        for (int j = 0; j < 4; j++) o[i][j] = 0.f;
    }
    __syncthreads();

    for (int kt = 0; kt <= qt; kt++) {
        const int k0 = kt * 64;
        {
            const float* kp = Kg + base + (size_t)(k0 + lr) * Ee;
            const float* vp = Vg + base + (size_t)(k0 + lr) * Ee;
            #pragma unroll
            for (int c = 0; c < 4; c++) {
                const int col = (c * 4 + lq) * 4;
                float4 kv = *(const float4*)(kp + col);
                Kt[(col + 0) * LDA + lr] = kv.x;
                Kt[(col + 1) * LDA + lr] = kv.y;
                Kt[(col + 2) * LDA + lr] = kv.z;
                Kt[(col + 3) * LDA + lr] = kv.w;
                *(float4*)&Vs[lr * LDA + col] = *(const float4*)(vp + col);
            }
        }
        __syncthreads();

        float s[4][4];
        #pragma unroll
        for (int i = 0; i < 4; i++)
            #pragma unroll
            for (int j = 0; j < 4; j++) s[i][j] = 0.f;

        #pragma unroll
        for (int d4 = 0; d4 < 16; d4++) {
            float qa[4][4], ka[4][4];
            #pragma unroll
            for (int i = 0; i < 4; i++) {
                float4 v = *(const float4*)&Qs[(ty * 4 + i) * LDA + d4 * 4];
                qa[i][0] = v.x; qa[i][1] = v.y; qa[i][2] = v.z; qa[i][3] = v.w;
            }
            #pragma unroll
            for (int dd = 0; dd < 4; dd++) {
                float4 v = *(const float4*)&Kt[(d4 * 4 + dd) * LDA + tx * 4];
                ka[dd][0] = v.x; ka[dd][1] = v.y; ka[dd][2] = v.z; ka[dd][3] = v.w;
            }
            #pragma unroll
            for (int dd = 0; dd < 4; dd++)
                #pragma unroll
                for (int i = 0; i < 4; i++)
                    #pragma unroll
                    for (int j = 0; j < 4; j++)
                        s[i][j] = fmaf(qa[i][dd], ka[dd][j], s[i][j]);
        }

        const bool diag = (kt == qt);
        #pragma unroll
        for (int i = 0; i < 4; i++) {
            const int qi = ty * 4 + i;
            #pragma unroll
            for (int j = 0; j < 4; j++) {
                float val = s[i][j] * 0.125f;
                if (diag && (tx * 4 + j) > qi) val = -1e30f;
                s[i][j] = val;
            }
            float tm = fmaxf(fmaxf(s[i][0], s[i][1]), fmaxf(s[i][2], s[i][3]));
            #pragma unroll
            for (int off = 8; off; off >>= 1)
                tm = fmaxf(tm, __shfl_xor_sync(0xffffffffu, tm, off));
            const float mn    = fmaxf(m[i], tm);
            const float alpha = __expf(m[i] - mn);
            float rs = 0.f;
            #pragma unroll
            for (int j = 0; j < 4; j++) {
                float p = __expf(s[i][j] - mn);
                s[i][j] = p; rs += p;
            }
            #pragma unroll
            for (int off = 8; off; off >>= 1)
                rs += __shfl_xor_sync(0xffffffffu, rs, off);
            l[i] = l[i] * alpha + rs;
            m[i] = mn;
            #pragma unroll
            for (int j = 0; j < 4; j++) o[i][j] *= alpha;
        }

        #pragma unroll
        for (int i = 0; i < 4; i++)
            *(float4*)&Ps[(ty * 4 + i) * LDA + tx * 4] =
                make_float4(s[i][0], s[i][1], s[i][2], s[i][3]);
        __syncthreads();

        #pragma unroll
        for (int j4 = 0; j4 < 16; j4++) {
            float pa[4][4], va[4][4];
            #pragma unroll
            for (int i = 0; i < 4; i++) {
                float4 v = *(const float4*)&Ps[(ty * 4 + i) * LDA + j4 * 4];
                pa[i][0] = v.x; pa[i][1] = v.y; pa[i][2] = v.z; pa[i][3] = v.w;
            }
            #pragma unroll
            for (int jj = 0; jj < 4; jj++) {
                float4 v = *(const float4*)&Vs[(j4 * 4 + jj) * LDA + tx * 4];
                va[jj][0] = v.x; va[jj][1] = v.y; va[jj][2] = v.z; va[jj][3] = v.w;
            }
            #pragma unroll
            for (int jj = 0; jj < 4; jj++)
                #pragma unroll
                for (int i = 0; i < 4; i++)
                    #pragma unroll
                    for (int d = 0; d < 4; d++)
                        o[i][d] = fmaf(pa[i][jj], va[jj][d], o[i][d]);
        }
        __syncthreads();
    }

    #pragma unroll
    for (int i = 0; i < 4; i++) {
        const float inv = 1.0f / l[i];
        const int row = q0 + ty * 4 + i;
        float* op = Og + base + (size_t)row * Ee + tx * 4;
        op[0] = rna(o[i][0] * inv); op[1] = rna(o[i][1] * inv);
        op[2] = rna(o[i][2] * inv); op[3] = rna(o[i][3] * inv);
    }
}

// ---------------------------------------------------------------------------
// Launch
// ---------------------------------------------------------------------------
extern "C" void kernel_launch(void* const* d_in, const int* in_sizes, int n_in,
                              void* d_out, int out_size)
{
    const float* x     = (const float*)d_in[0];
    const float* wq    = (const float*)d_in[1];
    const float* wk    = (const float*)d_in[2];
    const float* wv    = (const float*)d_in[3];
    const float* wo    = (const float*)d_in[4];
    const float* bo    = (const float*)d_in[5];
    const float* w1    = (const float*)d_in[6];
    const float* b1    = (const float*)d_in[7];
    const float* w2    = (const float*)d_in[8];
    const float* b2    = (const float*)d_in[9];
    const float* gamma = (const float*)d_in[10];
    const float* beta  = (const float*)d_in[11];
    float* out = (float*)d_out;

    float *xn, *q, *k, *v, *at, *res, *y, *hb;
    float *wqr, *wkr, *wvr, *wor, *w1r, *w2r;
    cudaGetSymbolAddress((void**)&xn,  g_xn);
    cudaGetSymbolAddress((void**)&q,   g_q);
    cudaGetSymbolAddress((void**)&k,   g_k);
    cudaGetSymbolAddress((void**)&v,   g_v);
    cudaGetSymbolAddress((void**)&at,  g_at);
    cudaGetSymbolAddress((void**)&res, g_res);
    cudaGetSymbolAddress((void**)&y,   g_y);
    cudaGetSymbolAddress((void**)&hb,  g_h);
    cudaGetSymbolAddress((void**)&wqr, g_wq);
    cudaGetSymbolAddress((void**)&wkr, g_wk);
    cudaGetSymbolAddress((void**)&wvr, g_wv);
    cudaGetSymbolAddress((void**)&wor, g_wo);
    cudaGetSymbolAddress((void**)&w1r, g_w1);
    cudaGetSymbolAddress((void**)&w2r, g_w2);

    const dim3 gqkv(Ee / 128, Mrows / 128, 3);
    const dim3 g768(Ee / 128, Mrows / 128);
    const dim3 g3072(FFf / 128, Mrows / 128);
    const int  smemFA = 4 * 64 * LDA * (int)sizeof(float);

    cudaFuncSetAttribute(flash_kernel, cudaFuncAttributeMaxDynamicSharedMemorySize, smemFA);
    cudaFuncSetAttribute(gemm_mma<EPI_NONE,3,false>,      cudaFuncAttributeMaxDynamicSharedMemorySize, SMEMB);
    cudaFuncSetAttribute(gemm_mma<EPI_BIAS_RES,1,false>,  cudaFuncAttributeMaxDynamicSharedMemorySize, SMEMB);
    cudaFuncSetAttribute(gemm_mma<EPI_BIAS_GELU,1,true>,  cudaFuncAttributeMaxDynamicSharedMemorySize, SMEMB);

    // Round weights to tf32-RN once (inside graph; deterministic)
    round_kernel<<<(Ee*Ee)/1024, 256>>>(wq, wqr, Ee*Ee);
    round_kernel<<<(Ee*Ee)/1024, 256>>>(wk, wkr, Ee*Ee);
    round_kernel<<<(Ee*Ee)/1024, 256>>>(wv, wvr, Ee*Ee);
    round_kernel<<<(Ee*Ee)/1024, 256>>>(wo, wor, Ee*Ee);
    round_kernel<<<(FFf*Ee)/1024, 256>>>(w1, w1r, FFf*Ee);
    round_kernel<<<(FFf*Ee)/1024, 256>>>(w2, w2r, Ee*FFf);

    ln_kernel<<<Mrows, 256>>>(x, gamma, beta, xn);

    gemm_mma<EPI_NONE,3,false><<<gqkv, 256, SMEMB>>>(xn, wqr, wkr, wvr, nullptr, nullptr,
                                                     q, k, v, Mrows, Ee, Ee);

    flash_kernel<<<dim3(Ss / 64, Hh, Bb), 256, smemFA>>>(q, k, v, at);

    gemm_mma<EPI_BIAS_RES,1,false><<<g768, 256, SMEMB>>>(at, wor, wor, wor, bo, x,
                                                         res, res, res, Mrows, Ee, Ee);

    ln_kernel<<<Mrows, 256>>>(res, gamma, beta, y);

    gemm_mma<EPI_BIAS_GELU,1,true><<<g3072, 256, SMEMB>>>(y, w1r, w1r, w1r, b1, nullptr,
                                                          hb, hb, hb, Mrows, FFf, Ee);
    gemm_mma<EPI_BIAS_RES,1,false><<<g768, 256, SMEMB>>>(hb, w2r, w2r, w2r, b2, res,
                                                         out, out, out, Mrows, Ee, FFf);
}

// round 6
// speedup vs baseline: 1.3379x; 1.3379x over previous
#include <cuda_runtime.h>
#include <math.h>
#include <stdint.h>

// Problem constants
#define Bb   2
#define Ss   2048
#define Ee   768
#define Hh   12
#define Dd   64
#define FFf  3072
#define Mrows (Bb*Ss)   // 4096

// ---------------------------------------------------------------------------
// Scratch (static device globals; no runtime allocation allowed)
// ---------------------------------------------------------------------------
__device__ float g_xn [Mrows*Ee];
__device__ float g_q  [Mrows*Ee];
__device__ float g_k  [Mrows*Ee];
__device__ float g_v  [Mrows*Ee];
__device__ float g_at [Mrows*Ee];
__device__ float g_res[Mrows*Ee];
__device__ float g_y  [Mrows*Ee];
__device__ float g_h  [Mrows*FFf];
// RN-rounded tf32 weight copies
__device__ float g_wq[Ee*Ee];
__device__ float g_wk[Ee*Ee];
__device__ float g_wv[Ee*Ee];
__device__ float g_wo[Ee*Ee];
__device__ float g_w1[FFf*Ee];
__device__ float g_w2[Ee*FFf];

// ---------------------------------------------------------------------------
// Helpers
// ---------------------------------------------------------------------------
__device__ __forceinline__ uint32_t smem_u32(const void* p) {
    uint32_t a;
    asm("{ .reg .u64 t; cvta.to.shared.u64 t, %1; cvt.u32.u64 %0, t; }"
        : "=r"(a) : "l"(p));
    return a;
}
__device__ __forceinline__ void cp16(uint32_t dst, const void* src) {
    asm volatile("cp.async.cg.shared.global [%0], [%1], 16;"
                 :: "r"(dst), "l"(src));
}
#define CP_COMMIT() asm volatile("cp.async.commit_group;" ::: "memory")
#define CP_WAIT(n)  asm volatile("cp.async.wait_group %0;" :: "n"(n) : "memory")

// round-to-nearest tf32 (kills truncation bias in mma operands)
__device__ __forceinline__ float rna(float x) {
    uint32_t u;
    asm("cvt.rna.tf32.f32 %0, %1;" : "=r"(u) : "f"(x));
    return __uint_as_float(u);
}

// D += A(16x8,row) * B(8x8,col as B^T rows)  tf32 inputs
__device__ __forceinline__ void mma_tf32(float* c, const uint32_t* a,
                                         uint32_t b0, uint32_t b1) {
    asm volatile(
        "mma.sync.aligned.m16n8k8.row.col.f32.tf32.tf32.f32 "
        "{%0,%1,%2,%3}, {%4,%5,%6,%7}, {%8,%9}, {%0,%1,%2,%3};"
        : "+f"(c[0]), "+f"(c[1]), "+f"(c[2]), "+f"(c[3])
        : "r"(a[0]), "r"(a[1]), "r"(a[2]), "r"(a[3]), "r"(b0), "r"(b1));
}

// ---------------------------------------------------------------------------
// Fused weight rounding: all six weights in ONE launch (segment dispatch)
// ---------------------------------------------------------------------------
__global__ void round_all(const float* __restrict__ wq, const float* __restrict__ wk,
                          const float* __restrict__ wv, const float* __restrict__ wo,
                          const float* __restrict__ w1, const float* __restrict__ w2,
                          float* __restrict__ dq, float* __restrict__ dk,
                          float* __restrict__ dv, float* __restrict__ dwo,
                          float* __restrict__ d1, float* __restrict__ d2)
{
    const int E4 = Ee * Ee / 4;        // 147456 float4s
    const int F4 = (FFf * Ee) / 4;     // 589824 float4s
    int i = blockIdx.x * blockDim.x + threadIdx.x;
    const float* s; float* d;
    if      (i < E4)          { s = wq; d = dq; }
    else if (i < 2*E4)        { s = wk; d = dk;  i -= E4; }
    else if (i < 3*E4)        { s = wv; d = dv;  i -= 2*E4; }
    else if (i < 4*E4)        { s = wo; d = dwo; i -= 3*E4; }
    else if (i < 4*E4 + F4)   { s = w1; d = d1;  i -= 4*E4; }
    else                      { s = w2; d = d2;  i -= 4*E4 + F4; }
    float4 v = ((const float4*)s)[i];
    v.x = rna(v.x); v.y = rna(v.y); v.z = rna(v.z); v.w = rna(v.w);
    ((float4*)d)[i] = v;
}
#define ROUND_BLOCKS ((4*(Ee*Ee/4) + 2*((FFf*Ee)/4)) / 256)   // 6912

// ---------------------------------------------------------------------------
// LayerNorm (outputs rounded: they feed GEMM A operands)
// ---------------------------------------------------------------------------
__global__ void ln_kernel(const float* __restrict__ X,
                          const float* __restrict__ gamma,
                          const float* __restrict__ beta,
                          float* __restrict__ Y)
{
    const int row = blockIdx.x;
    const float* x = X + (size_t)row * Ee;
    float*       y = Y + (size_t)row * Ee;
    const int t = threadIdx.x;

    float v0 = x[t], v1 = x[t + 256], v2 = x[t + 512];
    float s  = v0 + v1 + v2;

    __shared__ float red[8];
    #pragma unroll
    for (int off = 16; off; off >>= 1) s += __shfl_xor_sync(0xffffffffu, s, off);
    if ((t & 31) == 0) red[t >> 5] = s;
    __syncthreads();
    if (t < 8) {
        float r = red[t];
        #pragma unroll
        for (int off = 4; off; off >>= 1) r += __shfl_xor_sync(0xffu, r, off);
        if (t == 0) red[0] = r;
    }
    __syncthreads();
    const float mu = red[0] * (1.0f / Ee);
    __syncthreads();

    float d0 = v0 - mu, d1 = v1 - mu, d2 = v2 - mu;
    float q  = d0*d0 + d1*d1 + d2*d2;
    #pragma unroll
    for (int off = 16; off; off >>= 1) q += __shfl_xor_sync(0xffffffffu, q, off);
    if ((t & 31) == 0) red[t >> 5] = q;
    __syncthreads();
    if (t < 8) {
        float r = red[t];
        #pragma unroll
        for (int off = 4; off; off >>= 1) r += __shfl_xor_sync(0xffu, r, off);
        if (t == 0) red[0] = r;
    }
    __syncthreads();
    const float inv = rsqrtf(red[0] * (1.0f / Ee) + 1e-5f);

    y[t      ] = rna(d0 * inv * gamma[t      ] + beta[t      ]);
    y[t + 256] = rna(d1 * inv * gamma[t + 256] + beta[t + 256]);
    y[t + 512] = rna(d2 * inv * gamma[t + 512] + beta[t + 512]);
}

// ---------------------------------------------------------------------------
// tf32 tensor-core GEMM (unchanged from R5): C = A * B^T (+ epilogue)
// ---------------------------------------------------------------------------
enum { EPI_NONE = 0, EPI_BIAS = 1, EPI_BIAS_GELU = 2, EPI_BIAS_RES = 3 };

#define PITCH   68
#define TILEF   (128*PITCH)
#define STAGEB  (2*TILEF*4)
#define NSTAGE  3
#define SMEMB   (NSTAGE*STAGEB)

template <int EPI, int NQKV, bool ROUT>
__global__ __launch_bounds__(256, 1)
void gemm_mma(const float* __restrict__ A,
              const float* __restrict__ Bq, const float* __restrict__ Bk,
              const float* __restrict__ Bv,
              const float* __restrict__ bias, const float* __restrict__ R,
              float* __restrict__ Cq, float* __restrict__ Ck,
              float* __restrict__ Cv,
              int M, int N, int K)
{
    const float* Bm = Bq;
    float*       C  = Cq;
    if (NQKV == 3) {
        if (blockIdx.z == 1)      { Bm = Bk; C = Ck; }
        else if (blockIdx.z == 2) { Bm = Bv; C = Cv; }
    }

    extern __shared__ float sm[];

    const int t    = threadIdx.x;
    const int lane = t & 31;
    const int wid  = t >> 5;
    const int wr   = wid & 3;
    const int wc   = wid >> 2;
    const int mr   = wr * 32;
    const int nc0  = wc * 64;
    const int g    = lane >> 2;
    const int tg   = lane & 3;
    const int r0   = t >> 4;
    const int c4   = t & 15;

    const int bm = blockIdx.y * 128;
    const int bn = blockIdx.x * 128;

    float c[2][8][4];
    #pragma unroll
    for (int mt = 0; mt < 2; mt++)
        #pragma unroll
        for (int nt = 0; nt < 8; nt++)
            #pragma unroll
            for (int i = 0; i < 4; i++) c[mt][nt][i] = 0.f;

    const uint32_t sBase = smem_u32(sm);

    auto issue = [&](int ci) {
        const int st = ci % NSTAGE;
        const int k0 = ci << 6;
        const uint32_t dA = sBase + (uint32_t)st * STAGEB;
        const uint32_t dB = dA + TILEF * 4;
        #pragma unroll
        for (int p = 0; p < 8; p++) {
            const int row = p * 16 + r0;
            const uint32_t so = (uint32_t)(row * PITCH + c4 * 4) * 4;
            cp16(dA + so, A  + (size_t)(bm + row) * K + k0 + c4 * 4);
            cp16(dB + so, Bm + (size_t)(bn + row) * K + k0 + c4 * 4);
        }
        CP_COMMIT();
    };

    const int nchunk = K >> 6;
    issue(0);
    issue(1);

    #pragma unroll 1
    for (int ci = 0; ci < nchunk; ci++) {
        if (ci + 2 < nchunk) { issue(ci + 2); CP_WAIT(2); }
        else if (ci + 1 < nchunk) { CP_WAIT(1); }
        else { CP_WAIT(0); }
        __syncthreads();

        const float* sa = sm + (ci % NSTAGE) * (2 * TILEF);
        const float* sb = sa + TILEF;

        uint32_t afr[2][8], bfr[2][16];

        auto ldfr = [&](int kk, uint32_t* af, uint32_t* bf) {
            const int kb = kk * 8;
            #pragma unroll
            for (int mt = 0; mt < 2; mt++) {
                const float* p0 = sa + (mr + mt * 16 + g) * PITCH + kb + tg;
                const float* p1 = p0 + 8 * PITCH;
                af[mt*4+0] = __float_as_uint(p0[0]);
                af[mt*4+1] = __float_as_uint(p1[0]);
                af[mt*4+2] = __float_as_uint(p0[4]);
                af[mt*4+3] = __float_as_uint(p1[4]);
            }
            #pragma unroll
            for (int nt = 0; nt < 8; nt++) {
                const float* q0 = sb + (nc0 + nt * 8 + g) * PITCH + kb + tg;
                bf[nt*2+0] = __float_as_uint(q0[0]);
                bf[nt*2+1] = __float_as_uint(q0[4]);
            }
        };

        ldfr(0, afr[0], bfr[0]);
        #pragma unroll
        for (int kk = 0; kk < 8; kk++) {
            const int cur = kk & 1;
            if (kk < 7) ldfr(kk + 1, afr[cur ^ 1], bfr[cur ^ 1]);
            #pragma unroll
            for (int nt = 0; nt < 8; nt++) {
                mma_tf32(c[0][nt], &afr[cur][0], bfr[cur][nt*2], bfr[cur][nt*2+1]);
                mma_tf32(c[1][nt], &afr[cur][4], bfr[cur][nt*2], bfr[cur][nt*2+1]);
            }
        }
        __syncthreads();
    }

    #pragma unroll
    for (int mt = 0; mt < 2; mt++) {
        #pragma unroll
        for (int half = 0; half < 2; half++) {
            const int row = bm + mr + mt * 16 + g + half * 8;
            #pragma unroll
            for (int nt = 0; nt < 8; nt++) {
                const int col = bn + nc0 + nt * 8 + 2 * tg;
                float2 v = make_float2(c[mt][nt][half * 2 + 0],
                                       c[mt][nt][half * 2 + 1]);
                if (EPI >= EPI_BIAS) {
                    float2 bb = *(const float2*)(bias + col);
                    v.x += bb.x; v.y += bb.y;
                }
                if (EPI == EPI_BIAS_GELU) {
                    v.x = 0.5f * v.x * (1.0f + erff(v.x * 0.70710678118654752f));
                    v.y = 0.5f * v.y * (1.0f + erff(v.y * 0.70710678118654752f));
                }
                if (EPI == EPI_BIAS_RES) {
                    float2 rr = *(const float2*)(R + (size_t)row * N + col);
                    v.x += rr.x; v.y += rr.y;
                }
                if (ROUT) { v.x = rna(v.x); v.y = rna(v.y); }
                *(float2*)(C + (size_t)row * N + col) = v;
            }
        }
    }
}

// ---------------------------------------------------------------------------
// Flash attention on tensor cores (tf32 mma, fp32 softmax, causal)
// 128 threads / 4 warps; 64-query tile; Q fragments register-resident.
// smem: Ks[64][68] (row-major, = mma B layout), Vt[64][68] (d-major),
//       Ps[64][68] (P round-trip; doubles as Q staging at init) = 52224 B
// ---------------------------------------------------------------------------
#define FLDA 68
#define FSMEM (3*64*FLDA*4)

__global__ __launch_bounds__(128, 3)
void flash_mma(const float* __restrict__ Qg, const float* __restrict__ Kg,
               const float* __restrict__ Vg, float* __restrict__ Og)
{
    extern __shared__ float sm[];
    float* Ks = sm;
    float* Vt = sm + 64 * FLDA;
    float* Ps = sm + 2 * 64 * FLDA;   // also Q staging at init

    const int qt = blockIdx.x, h = blockIdx.y, b = blockIdx.z;
    const int q0 = qt * 64;
    const int t = threadIdx.x, wid = t >> 5, lane = t & 31;
    const int g = lane >> 2, tg = lane & 3;
    const int r0l = wid * 16 + g;          // local row (first of pair)
    const size_t base = (size_t)b * Ss * Ee + h * Dd;

    // stage Q (row-major) into Ps region, extract register fragments
    #pragma unroll
    for (int p = 0; p < 8; p++) {
        const int idx = p * 128 + t, row = idx >> 4, c4 = idx & 15;
        *(float4*)&Ps[row * FLDA + c4 * 4] =
            *(const float4*)(Qg + base + (size_t)(q0 + row) * Ee + c4 * 4);
    }
    __syncthreads();
    uint32_t qf[8][4];
    #pragma unroll
    for (int kk = 0; kk < 8; kk++) {
        const float* p0 = Ps + r0l * FLDA + kk * 8 + tg;
        qf[kk][0] = __float_as_uint(p0[0]);
        qf[kk][1] = __float_as_uint(p0[8 * FLDA]);
        qf[kk][2] = __float_as_uint(p0[4]);
        qf[kk][3] = __float_as_uint(p0[8 * FLDA + 4]);
    }
    // (no extra sync: first Ps overwrite happens after the staging sync below)

    float m0 = -INFINITY, m1 = -INFINITY, l0 = 0.f, l1 = 0.f;
    float of[8][4];
    #pragma unroll
    for (int nt = 0; nt < 8; nt++) { of[nt][0]=of[nt][1]=of[nt][2]=of[nt][3]=0.f; }

    for (int kt = 0; kt <= qt; kt++) {
        const int k0 = kt * 64;
        // stage K (row-major) and V (transposed to d-major)
        #pragma unroll
        for (int p = 0; p < 8; p++) {
            const int idx = p * 128 + t, row = idx >> 4, c4 = idx & 15;
            *(float4*)&Ks[row * FLDA + c4 * 4] =
                *(const float4*)(Kg + base + (size_t)(k0 + row) * Ee + c4 * 4);
            float4 vv = *(const float4*)(Vg + base + (size_t)(k0 + row) * Ee + c4 * 4);
            Vt[(c4 * 4 + 0) * FLDA + row] = vv.x;
            Vt[(c4 * 4 + 1) * FLDA + row] = vv.y;
            Vt[(c4 * 4 + 2) * FLDA + row] = vv.z;
            Vt[(c4 * 4 + 3) * FLDA + row] = vv.w;
        }
        __syncthreads();

        // S = Q @ K^T (16x64 per warp)
        float cS[8][4];
        #pragma unroll
        for (int nt = 0; nt < 8; nt++) { cS[nt][0]=cS[nt][1]=cS[nt][2]=cS[nt][3]=0.f; }
        #pragma unroll
        for (int kk = 0; kk < 8; kk++) {
            #pragma unroll
            for (int nt = 0; nt < 8; nt++) {
                const float* bp = Ks + (nt * 8 + g) * FLDA + kk * 8 + tg;
                mma_tf32(cS[nt], qf[kk],
                         __float_as_uint(bp[0]), __float_as_uint(bp[4]));
            }
        }

        // fp32 online softmax on fragments (rows r0l, r0l+8)
        const bool diag = (kt == qt);
        float mx0 = -INFINITY, mx1 = -INFINITY;
        #pragma unroll
        for (int nt = 0; nt < 8; nt++) {
            float v0 = cS[nt][0] * 0.125f, v1 = cS[nt][1] * 0.125f;
            float v2 = cS[nt][2] * 0.125f, v3 = cS[nt][3] * 0.125f;
            if (diag) {
                const int j0 = nt * 8 + 2 * tg;     // tile-local column
                if (j0     > r0l)     v0 = -1e30f;
                if (j0 + 1 > r0l)     v1 = -1e30f;
                if (j0     > r0l + 8) v2 = -1e30f;
                if (j0 + 1 > r0l + 8) v3 = -1e30f;
            }
            cS[nt][0] = v0; cS[nt][1] = v1; cS[nt][2] = v2; cS[nt][3] = v3;
            mx0 = fmaxf(mx0, fmaxf(v0, v1));
            mx1 = fmaxf(mx1, fmaxf(v2, v3));
        }
        mx0 = fmaxf(mx0, __shfl_xor_sync(0xffffffffu, mx0, 1));
        mx0 = fmaxf(mx0, __shfl_xor_sync(0xffffffffu, mx0, 2));
        mx1 = fmaxf(mx1, __shfl_xor_sync(0xffffffffu, mx1, 1));
        mx1 = fmaxf(mx1, __shfl_xor_sync(0xffffffffu, mx1, 2));
        const float mn0 = fmaxf(m0, mx0), mn1 = fmaxf(m1, mx1);
        const float a0 = __expf(m0 - mn0), a1 = __expf(m1 - mn1);
        float rs0 = 0.f, rs1 = 0.f;
        #pragma unroll
        for (int nt = 0; nt < 8; nt++) {
            const float p0e = __expf(cS[nt][0] - mn0);
            const float p1e = __expf(cS[nt][1] - mn0);
            const float p2e = __expf(cS[nt][2] - mn1);
            const float p3e = __expf(cS[nt][3] - mn1);
            cS[nt][0] = p0e; cS[nt][1] = p1e; cS[nt][2] = p2e; cS[nt][3] = p3e;
            rs0 += p0e + p1e; rs1 += p2e + p3e;
        }
        rs0 += __shfl_xor_sync(0xffffffffu, rs0, 1);
        rs0 += __shfl_xor_sync(0xffffffffu, rs0, 2);
        rs1 += __shfl_xor_sync(0xffffffffu, rs1, 1);
        rs1 += __shfl_xor_sync(0xffffffffu, rs1, 2);
        l0 = l0 * a0 + rs0; l1 = l1 * a1 + rs1;
        m0 = mn0; m1 = mn1;
        #pragma unroll
        for (int nt = 0; nt < 8; nt++) {
            of[nt][0] *= a0; of[nt][1] *= a0;
            of[nt][2] *= a1; of[nt][3] *= a1;
        }

        // store P tile (rounded; C layout -> A layout needs smem round-trip)
        #pragma unroll
        for (int nt = 0; nt < 8; nt++) {
            *(float2*)&Ps[r0l * FLDA + nt * 8 + 2 * tg] =
                make_float2(rna(cS[nt][0]), rna(cS[nt][1]));
            *(float2*)&Ps[(r0l + 8) * FLDA + nt * 8 + 2 * tg] =
                make_float2(rna(cS[nt][2]), rna(cS[nt][3]));
        }
        __syncthreads();

        // O += P @ V
        #pragma unroll
        for (int kk = 0; kk < 8; kk++) {
            const float* pp = Ps + r0l * FLDA + kk * 8 + tg;
            uint32_t pa[4];
            pa[0] = __float_as_uint(pp[0]);
            pa[1] = __float_as_uint(pp[8 * FLDA]);
            pa[2] = __float_as_uint(pp[4]);
            pa[3] = __float_as_uint(pp[8 * FLDA + 4]);
            #pragma unroll
            for (int nt = 0; nt < 8; nt++) {
                const float* bp = Vt + (nt * 8 + g) * FLDA + kk * 8 + tg;
                mma_tf32(of[nt], pa,
                         __float_as_uint(bp[0]), __float_as_uint(bp[4]));
            }
        }
        __syncthreads();
    }

    // normalize + write (rounded: feeds O-proj A operand)
    const float i0 = 1.f / l0, i1 = 1.f / l1;
    #pragma unroll
    for (int nt = 0; nt < 8; nt++) {
        const int col = nt * 8 + 2 * tg;
        float* o0 = Og + base + (size_t)(q0 + r0l) * Ee + col;
        float* o1 = o0 + 8 * Ee;
        *(float2*)o0 = make_float2(rna(of[nt][0] * i0), rna(of[nt][1] * i0));
        *(float2*)o1 = make_float2(rna(of[nt][2] * i1), rna(of[nt][3] * i1));
    }
}

// ---------------------------------------------------------------------------
// Launch
// ---------------------------------------------------------------------------
extern "C" void kernel_launch(void* const* d_in, const int* in_sizes, int n_in,
                              void* d_out, int out_size)
{
    const float* x     = (const float*)d_in[0];
    const float* wq    = (const float*)d_in[1];
    const float* wk    = (const float*)d_in[2];
    const float* wv    = (const float*)d_in[3];
    const float* wo    = (const float*)d_in[4];
    const float* bo    = (const float*)d_in[5];
    const float* w1    = (const float*)d_in[6];
    const float* b1    = (const float*)d_in[7];
    const float* w2    = (const float*)d_in[8];
    const float* b2    = (const float*)d_in[9];
    const float* gamma = (const float*)d_in[10];
    const float* beta  = (const float*)d_in[11];
    float* out = (float*)d_out;

    float *xn, *q, *k, *v, *at, *res, *y, *hb;
    float *wqr, *wkr, *wvr, *wor, *w1r, *w2r;
    cudaGetSymbolAddress((void**)&xn,  g_xn);
    cudaGetSymbolAddress((void**)&q,   g_q);
    cudaGetSymbolAddress((void**)&k,   g_k);
    cudaGetSymbolAddress((void**)&v,   g_v);
    cudaGetSymbolAddress((void**)&at,  g_at);
    cudaGetSymbolAddress((void**)&res, g_res);
    cudaGetSymbolAddress((void**)&y,   g_y);
    cudaGetSymbolAddress((void**)&hb,  g_h);
    cudaGetSymbolAddress((void**)&wqr, g_wq);
    cudaGetSymbolAddress((void**)&wkr, g_wk);
    cudaGetSymbolAddress((void**)&wvr, g_wv);
    cudaGetSymbolAddress((void**)&wor, g_wo);
    cudaGetSymbolAddress((void**)&w1r, g_w1);
    cudaGetSymbolAddress((void**)&w2r, g_w2);

    const dim3 gqkv(Ee / 128, Mrows / 128, 3);
    const dim3 g768(Ee / 128, Mrows / 128);
    const dim3 g3072(FFf / 128, Mrows / 128);

    cudaFuncSetAttribute(flash_mma, cudaFuncAttributeMaxDynamicSharedMemorySize, FSMEM);
    cudaFuncSetAttribute(gemm_mma<EPI_NONE,3,true>,       cudaFuncAttributeMaxDynamicSharedMemorySize, SMEMB);
    cudaFuncSetAttribute(gemm_mma<EPI_BIAS_RES,1,false>,  cudaFuncAttributeMaxDynamicSharedMemorySize, SMEMB);
    cudaFuncSetAttribute(gemm_mma<EPI_BIAS_GELU,1,true>,  cudaFuncAttributeMaxDynamicSharedMemorySize, SMEMB);

    round_all<<<ROUND_BLOCKS, 256>>>(wq, wk, wv, wo, w1, w2,
                                     wqr, wkr, wvr, wor, w1r, w2r);

    ln_kernel<<<Mrows, 256>>>(x, gamma, beta, xn);

    gemm_mma<EPI_NONE,3,true><<<gqkv, 256, SMEMB>>>(xn, wqr, wkr, wvr, nullptr, nullptr,
                                                    q, k, v, Mrows, Ee, Ee);

    flash_mma<<<dim3(Ss / 64, Hh, Bb), 128, FSMEM>>>(q, k, v, at);

    gemm_mma<EPI_BIAS_RES,1,false><<<g768, 256, SMEMB>>>(at, wor, wor, wor, bo, x,
                                                         res, res, res, Mrows, Ee, Ee);

    ln_kernel<<<Mrows, 256>>>(res, gamma, beta, y);

    gemm_mma<EPI_BIAS_GELU,1,true><<<g3072, 256, SMEMB>>>(y, w1r, w1r, w1r, b1, nullptr,
                                                          hb, hb, hb, Mrows, FFf, Ee);
    gemm_mma<EPI_BIAS_RES,1,false><<<g768, 256, SMEMB>>>(hb, w2r, w2r, w2r, b2, res,
                                                         out, out, out, Mrows, Ee, FFf);
}

// round 7
// speedup vs baseline: 1.3594x; 1.0161x over previous
#include <cuda_runtime.h>
#include <math.h>
#include <stdint.h>

// Problem constants
#define Bb   2
#define Ss   2048
#define Ee   768
#define Hh   12
#define Dd   64
#define FFf  3072
#define Mrows (Bb*Ss)   // 4096

// ---------------------------------------------------------------------------
// Scratch
// ---------------------------------------------------------------------------
__device__ float g_xn [Mrows*Ee];
__device__ float g_q  [Mrows*Ee];
__device__ float g_k  [Mrows*Ee];
__device__ float g_v  [Mrows*Ee];
__device__ float g_at [Mrows*Ee];
__device__ float g_res[Mrows*Ee];
__device__ float g_y  [Mrows*Ee];
__device__ float g_h  [Mrows*FFf];
__device__ float g_wq[Ee*Ee];
__device__ float g_wk[Ee*Ee];
__device__ float g_wv[Ee*Ee];
__device__ float g_wo[Ee*Ee];
__device__ float g_w1[FFf*Ee];
__device__ float g_w2[Ee*FFf];

// ---------------------------------------------------------------------------
// Helpers
// ---------------------------------------------------------------------------
__device__ __forceinline__ uint32_t smem_u32(const void* p) {
    uint32_t a;
    asm("{ .reg .u64 t; cvta.to.shared.u64 t, %1; cvt.u32.u64 %0, t; }"
        : "=r"(a) : "l"(p));
    return a;
}
__device__ __forceinline__ void cp16(uint32_t dst, const void* src) {
    asm volatile("cp.async.cg.shared.global [%0], [%1], 16;"
                 :: "r"(dst), "l"(src));
}
#define CP_COMMIT() asm volatile("cp.async.commit_group;" ::: "memory")
#define CP_WAIT(n)  asm volatile("cp.async.wait_group %0;" :: "n"(n) : "memory")

__device__ __forceinline__ float rna(float x) {
    uint32_t u;
    asm("cvt.rna.tf32.f32 %0, %1;" : "=r"(u) : "f"(x));
    return __uint_as_float(u);
}

__device__ __forceinline__ void mma_tf32(float* c, const uint32_t* a,
                                         uint32_t b0, uint32_t b1) {
    asm volatile(
        "mma.sync.aligned.m16n8k8.row.col.f32.tf32.tf32.f32 "
        "{%0,%1,%2,%3}, {%4,%5,%6,%7}, {%8,%9}, {%0,%1,%2,%3};"
        : "+f"(c[0]), "+f"(c[1]), "+f"(c[2]), "+f"(c[3])
        : "r"(a[0]), "r"(a[1]), "r"(a[2]), "r"(a[3]), "r"(b0), "r"(b1));
}

// ---------------------------------------------------------------------------
// Fused weight rounding (one launch)
// ---------------------------------------------------------------------------
__global__ void round_all(const float* __restrict__ wq, const float* __restrict__ wk,
                          const float* __restrict__ wv, const float* __restrict__ wo,
                          const float* __restrict__ w1, const float* __restrict__ w2,
                          float* __restrict__ dq, float* __restrict__ dk,
                          float* __restrict__ dv, float* __restrict__ dwo,
                          float* __restrict__ d1, float* __restrict__ d2)
{
    const int E4 = Ee * Ee / 4;
    const int F4 = (FFf * Ee) / 4;
    int i = blockIdx.x * blockDim.x + threadIdx.x;
    const float* s; float* d;
    if      (i < E4)          { s = wq; d = dq; }
    else if (i < 2*E4)        { s = wk; d = dk;  i -= E4; }
    else if (i < 3*E4)        { s = wv; d = dv;  i -= 2*E4; }
    else if (i < 4*E4)        { s = wo; d = dwo; i -= 3*E4; }
    else if (i < 4*E4 + F4)   { s = w1; d = d1;  i -= 4*E4; }
    else                      { s = w2; d = d2;  i -= 4*E4 + F4; }
    float4 v = ((const float4*)s)[i];
    v.x = rna(v.x); v.y = rna(v.y); v.z = rna(v.z); v.w = rna(v.w);
    ((float4*)d)[i] = v;
}
#define ROUND_BLOCKS ((4*(Ee*Ee/4) + 2*((FFf*Ee)/4)) / 256)

// ---------------------------------------------------------------------------
// LayerNorm (outputs rounded)
// ---------------------------------------------------------------------------
__global__ void ln_kernel(const float* __restrict__ X,
                          const float* __restrict__ gamma,
                          const float* __restrict__ beta,
                          float* __restrict__ Y)
{
    const int row = blockIdx.x;
    const float* x = X + (size_t)row * Ee;
    float*       y = Y + (size_t)row * Ee;
    const int t = threadIdx.x;

    float v0 = x[t], v1 = x[t + 256], v2 = x[t + 512];
    float s  = v0 + v1 + v2;

    __shared__ float red[8];
    #pragma unroll
    for (int off = 16; off; off >>= 1) s += __shfl_xor_sync(0xffffffffu, s, off);
    if ((t & 31) == 0) red[t >> 5] = s;
    __syncthreads();
    if (t < 8) {
        float r = red[t];
        #pragma unroll
        for (int off = 4; off; off >>= 1) r += __shfl_xor_sync(0xffu, r, off);
        if (t == 0) red[0] = r;
    }
    __syncthreads();
    const float mu = red[0] * (1.0f / Ee);
    __syncthreads();

    float d0 = v0 - mu, d1 = v1 - mu, d2 = v2 - mu;
    float q  = d0*d0 + d1*d1 + d2*d2;
    #pragma unroll
    for (int off = 16; off; off >>= 1) q += __shfl_xor_sync(0xffffffffu, q, off);
    if ((t & 31) == 0) red[t >> 5] = q;
    __syncthreads();
    if (t < 8) {
        float r = red[t];
        #pragma unroll
        for (int off = 4; off; off >>= 1) r += __shfl_xor_sync(0xffu, r, off);
        if (t == 0) red[0] = r;
    }
    __syncthreads();
    const float inv = rsqrtf(red[0] * (1.0f / Ee) + 1e-5f);

    y[t      ] = rna(d0 * inv * gamma[t      ] + beta[t      ]);
    y[t + 256] = rna(d1 * inv * gamma[t + 256] + beta[t + 256]);
    y[t + 512] = rna(d2 * inv * gamma[t + 512] + beta[t + 512]);
}

// ---------------------------------------------------------------------------
// tf32 GEMM: C = A * B^T (+ epilogue). CTA 128x128x64, 512 threads,
// 16 warps (4x4), warp tile 32x32 -> 4 warps/SMSP to hide LDS latency.
// ---------------------------------------------------------------------------
enum { EPI_NONE = 0, EPI_BIAS = 1, EPI_BIAS_GELU = 2, EPI_BIAS_RES = 3 };

#define PITCH   68
#define TILEF   (128*PITCH)
#define STAGEB  (2*TILEF*4)
#define NSTAGE  3
#define SMEMB   (NSTAGE*STAGEB)

template <int EPI, int NQKV, bool ROUT>
__global__ __launch_bounds__(512, 1)
void gemm_mma(const float* __restrict__ A,
              const float* __restrict__ Bq, const float* __restrict__ Bk,
              const float* __restrict__ Bv,
              const float* __restrict__ bias, const float* __restrict__ R,
              float* __restrict__ Cq, float* __restrict__ Ck,
              float* __restrict__ Cv,
              int M, int N, int K)
{
    const float* Bm = Bq;
    float*       C  = Cq;
    if (NQKV == 3) {
        if (blockIdx.z == 1)      { Bm = Bk; C = Ck; }
        else if (blockIdx.z == 2) { Bm = Bv; C = Cv; }
    }

    extern __shared__ float sm[];

    const int t    = threadIdx.x;
    const int lane = t & 31;
    const int wid  = t >> 5;            // 0..15
    const int wr   = wid & 3;           // 4x4 warp grid
    const int wc   = wid >> 2;
    const int mr   = wr * 32;
    const int nc0  = wc * 32;
    const int g    = lane >> 2;
    const int tg   = lane & 3;

    const int bm = blockIdx.y * 128;
    const int bn = blockIdx.x * 128;

    float c[2][4][4];
    #pragma unroll
    for (int mt = 0; mt < 2; mt++)
        #pragma unroll
        for (int nt = 0; nt < 4; nt++)
            #pragma unroll
            for (int i = 0; i < 4; i++) c[mt][nt][i] = 0.f;

    const uint32_t sBase = smem_u32(sm);

    auto issue = [&](int ci) {
        const int st = ci % NSTAGE;
        const int k0 = ci << 6;
        const uint32_t dA = sBase + (uint32_t)st * STAGEB;
        const uint32_t dB = dA + TILEF * 4;
        #pragma unroll
        for (int p = 0; p < 4; p++) {      // 512 threads * 4 = 2048 float4
            const int idx = p * 512 + t;
            const int row = idx >> 4;
            const int c4  = idx & 15;
            const uint32_t so = (uint32_t)(row * PITCH + c4 * 4) * 4;
            cp16(dA + so, A  + (size_t)(bm + row) * K + k0 + c4 * 4);
            cp16(dB + so, Bm + (size_t)(bn + row) * K + k0 + c4 * 4);
        }
        CP_COMMIT();
    };

    const int nchunk = K >> 6;
    issue(0);
    issue(1);

    #pragma unroll 1
    for (int ci = 0; ci < nchunk; ci++) {
        if (ci + 2 < nchunk) { issue(ci + 2); CP_WAIT(2); }
        else if (ci + 1 < nchunk) { CP_WAIT(1); }
        else { CP_WAIT(0); }
        __syncthreads();

        const float* sa = sm + (ci % NSTAGE) * (2 * TILEF);
        const float* sb = sa + TILEF;

        uint32_t afr[2][8], bfr[2][8];

        auto ldfr = [&](int kk, uint32_t* af, uint32_t* bf) {
            const int kb = kk * 8;
            #pragma unroll
            for (int mt = 0; mt < 2; mt++) {
                const float* p0 = sa + (mr + mt * 16 + g) * PITCH + kb + tg;
                const float* p1 = p0 + 8 * PITCH;
                af[mt*4+0] = __float_as_uint(p0[0]);
                af[mt*4+1] = __float_as_uint(p1[0]);
                af[mt*4+2] = __float_as_uint(p0[4]);
                af[mt*4+3] = __float_as_uint(p1[4]);
            }
            #pragma unroll
            for (int nt = 0; nt < 4; nt++) {
                const float* q0 = sb + (nc0 + nt * 8 + g) * PITCH + kb + tg;
                bf[nt*2+0] = __float_as_uint(q0[0]);
                bf[nt*2+1] = __float_as_uint(q0[4]);
            }
        };

        ldfr(0, afr[0], bfr[0]);
        #pragma unroll
        for (int kk = 0; kk < 8; kk++) {
            const int cur = kk & 1;
            if (kk < 7) ldfr(kk + 1, afr[cur ^ 1], bfr[cur ^ 1]);
            #pragma unroll
            for (int nt = 0; nt < 4; nt++) {
                mma_tf32(c[0][nt], &afr[cur][0], bfr[cur][nt*2], bfr[cur][nt*2+1]);
                mma_tf32(c[1][nt], &afr[cur][4], bfr[cur][nt*2], bfr[cur][nt*2+1]);
            }
        }
        __syncthreads();
    }

    #pragma unroll
    for (int mt = 0; mt < 2; mt++) {
        #pragma unroll
        for (int half = 0; half < 2; half++) {
            const int row = bm + mr + mt * 16 + g + half * 8;
            #pragma unroll
            for (int nt = 0; nt < 4; nt++) {
                const int col = bn + nc0 + nt * 8 + 2 * tg;
                float2 v = make_float2(c[mt][nt][half * 2 + 0],
                                       c[mt][nt][half * 2 + 1]);
                if (EPI >= EPI_BIAS) {
                    float2 bb = *(const float2*)(bias + col);
                    v.x += bb.x; v.y += bb.y;
                }
                if (EPI == EPI_BIAS_GELU) {
                    v.x = 0.5f * v.x * (1.0f + erff(v.x * 0.70710678118654752f));
                    v.y = 0.5f * v.y * (1.0f + erff(v.y * 0.70710678118654752f));
                }
                if (EPI == EPI_BIAS_RES) {
                    float2 rr = *(const float2*)(R + (size_t)row * N + col);
                    v.x += rr.x; v.y += rr.y;
                }
                if (ROUT) { v.x = rna(v.x); v.y = rna(v.y); }
                *(float2*)(C + (size_t)row * N + col) = v;
            }
        }
    }
}

// ---------------------------------------------------------------------------
// Flash attention (tf32 mma): V kept ROW-major (conflict-free staging),
// cp.async double-buffered K/V prefetch, reversed qt order for tail balance.
// smem: Ks[2],Vs[2],Ps = 5 * 64*68 floats = 87040 B -> 2 CTAs/SM
// ---------------------------------------------------------------------------
#define FLDA 68
#define FT   (64*FLDA)
#define FSMEM (5*FT*4)

__global__ __launch_bounds__(128, 2)
void flash_mma(const float* __restrict__ Qg, const float* __restrict__ Kg,
               const float* __restrict__ Vg, float* __restrict__ Og)
{
    extern __shared__ float sm[];
    float* Ps = sm + 4 * FT;

    const int qt = (int)gridDim.x - 1 - (int)blockIdx.x;   // biggest first
    const int h = blockIdx.y, b = blockIdx.z;
    const int q0 = qt * 64;
    const int t = threadIdx.x, wid = t >> 5, lane = t & 31;
    const int g = lane >> 2, tg = lane & 3;
    const int r0l = wid * 16 + g;
    const size_t base = (size_t)b * Ss * Ee + h * Dd;
    const uint32_t sBase = smem_u32(sm);

    // stage Q into Ps, extract register fragments
    #pragma unroll
    for (int p = 0; p < 8; p++) {
        const int idx = p * 128 + t, row = idx >> 4, c4 = idx & 15;
        *(float4*)&Ps[row * FLDA + c4 * 4] =
            *(const float4*)(Qg + base + (size_t)(q0 + row) * Ee + c4 * 4);
    }
    __syncthreads();
    uint32_t qf[8][4];
    #pragma unroll
    for (int kk = 0; kk < 8; kk++) {
        const float* p0 = Ps + r0l * FLDA + kk * 8 + tg;
        qf[kk][0] = __float_as_uint(p0[0]);
        qf[kk][1] = __float_as_uint(p0[8 * FLDA]);
        qf[kk][2] = __float_as_uint(p0[4]);
        qf[kk][3] = __float_as_uint(p0[8 * FLDA + 4]);
    }

    // K/V staging via cp.async (double buffered)
    auto issue = [&](int kt) {
        const int buf = kt & 1;
        const int k0 = kt * 64;
        const uint32_t dK = sBase + (uint32_t)buf * (2 * FT) * 4;
        const uint32_t dV = dK + FT * 4;
        #pragma unroll
        for (int p = 0; p < 8; p++) {
            const int idx = p * 128 + t, row = idx >> 4, c4 = idx & 15;
            const uint32_t so = (uint32_t)(row * FLDA + c4 * 4) * 4;
            cp16(dK + so, Kg + base + (size_t)(k0 + row) * Ee + c4 * 4);
            cp16(dV + so, Vg + base + (size_t)(k0 + row) * Ee + c4 * 4);
        }
        CP_COMMIT();
    };

    float m0 = -INFINITY, m1 = -INFINITY, l0 = 0.f, l1 = 0.f;
    float of[8][4];
    #pragma unroll
    for (int nt = 0; nt < 8; nt++) { of[nt][0]=of[nt][1]=of[nt][2]=of[nt][3]=0.f; }

    issue(0);

    for (int kt = 0; kt <= qt; kt++) {
        if (kt < qt) { issue(kt + 1); CP_WAIT(1); }
        else         { CP_WAIT(0); }
        __syncthreads();

        const float* Ks = sm + (kt & 1) * (2 * FT);
        const float* Vs = Ks + FT;

        // S = Q @ K^T
        float cS[8][4];
        #pragma unroll
        for (int nt = 0; nt < 8; nt++) { cS[nt][0]=cS[nt][1]=cS[nt][2]=cS[nt][3]=0.f; }
        #pragma unroll
        for (int kk = 0; kk < 8; kk++) {
            #pragma unroll
            for (int nt = 0; nt < 8; nt++) {
                const float* bp = Ks + (nt * 8 + g) * FLDA + kk * 8 + tg;
                mma_tf32(cS[nt], qf[kk],
                         __float_as_uint(bp[0]), __float_as_uint(bp[4]));
            }
        }

        // fp32 online softmax
        const bool diag = (kt == qt);
        float mx0 = -INFINITY, mx1 = -INFINITY;
        #pragma unroll
        for (int nt = 0; nt < 8; nt++) {
            float v0 = cS[nt][0] * 0.125f, v1 = cS[nt][1] * 0.125f;
            float v2 = cS[nt][2] * 0.125f, v3 = cS[nt][3] * 0.125f;
            if (diag) {
                const int j0 = nt * 8 + 2 * tg;
                if (j0     > r0l)     v0 = -1e30f;
                if (j0 + 1 > r0l)     v1 = -1e30f;
                if (j0     > r0l + 8) v2 = -1e30f;
                if (j0 + 1 > r0l + 8) v3 = -1e30f;
            }
            cS[nt][0] = v0; cS[nt][1] = v1; cS[nt][2] = v2; cS[nt][3] = v3;
            mx0 = fmaxf(mx0, fmaxf(v0, v1));
            mx1 = fmaxf(mx1, fmaxf(v2, v3));
        }
        mx0 = fmaxf(mx0, __shfl_xor_sync(0xffffffffu, mx0, 1));
        mx0 = fmaxf(mx0, __shfl_xor_sync(0xffffffffu, mx0, 2));
        mx1 = fmaxf(mx1, __shfl_xor_sync(0xffffffffu, mx1, 1));
        mx1 = fmaxf(mx1, __shfl_xor_sync(0xffffffffu, mx1, 2));
        const float mn0 = fmaxf(m0, mx0), mn1 = fmaxf(m1, mx1);
        const float a0 = __expf(m0 - mn0), a1 = __expf(m1 - mn1);
        float rs0 = 0.f, rs1 = 0.f;
        #pragma unroll
        for (int nt = 0; nt < 8; nt++) {
            const float p0e = __expf(cS[nt][0] - mn0);
            const float p1e = __expf(cS[nt][1] - mn0);
            const float p2e = __expf(cS[nt][2] - mn1);
            const float p3e = __expf(cS[nt][3] - mn1);
            cS[nt][0] = p0e; cS[nt][1] = p1e; cS[nt][2] = p2e; cS[nt][3] = p3e;
            rs0 += p0e + p1e; rs1 += p2e + p3e;
        }
        rs0 += __shfl_xor_sync(0xffffffffu, rs0, 1);
        rs0 += __shfl_xor_sync(0xffffffffu, rs0, 2);
        rs1 += __shfl_xor_sync(0xffffffffu, rs1, 1);
        rs1 += __shfl_xor_sync(0xffffffffu, rs1, 2);
        l0 = l0 * a0 + rs0; l1 = l1 * a1 + rs1;
        m0 = mn0; m1 = mn1;
        #pragma unroll
        for (int nt = 0; nt < 8; nt++) {
            of[nt][0] *= a0; of[nt][1] *= a0;
            of[nt][2] *= a1; of[nt][3] *= a1;
        }

        // P round-trip through smem (C->A fragment layout)
        #pragma unroll
        for (int nt = 0; nt < 8; nt++) {
            *(float2*)&Ps[r0l * FLDA + nt * 8 + 2 * tg] =
                make_float2(rna(cS[nt][0]), rna(cS[nt][1]));
            *(float2*)&Ps[(r0l + 8) * FLDA + nt * 8 + 2 * tg] =
                make_float2(rna(cS[nt][2]), rna(cS[nt][3]));
        }
        __syncthreads();

        // O += P @ V   (V row-major: B[k][n] = Vs[k*FLDA + n])
        #pragma unroll
        for (int kk = 0; kk < 8; kk++) {
            const float* pp = Ps + r0l * FLDA + kk * 8 + tg;
            uint32_t pa[4];
            pa[0] = __float_as_uint(pp[0]);
            pa[1] = __float_as_uint(pp[8 * FLDA]);
            pa[2] = __float_as_uint(pp[4]);
            pa[3] = __float_as_uint(pp[8 * FLDA + 4]);
            const float* vrow0 = Vs + (kk * 8 + tg) * FLDA;
            const float* vrow1 = vrow0 + 4 * FLDA;
            #pragma unroll
            for (int nt = 0; nt < 8; nt++) {
                mma_tf32(of[nt], pa,
                         __float_as_uint(vrow0[nt * 8 + g]),
                         __float_as_uint(vrow1[nt * 8 + g]));
            }
        }
        __syncthreads();
    }

    const float i0 = 1.f / l0, i1 = 1.f / l1;
    #pragma unroll
    for (int nt = 0; nt < 8; nt++) {
        const int col = nt * 8 + 2 * tg;
        float* o0 = Og + base + (size_t)(q0 + r0l) * Ee + col;
        float* o1 = o0 + 8 * Ee;
        *(float2*)o0 = make_float2(rna(of[nt][0] * i0), rna(of[nt][1] * i0));
        *(float2*)o1 = make_float2(rna(of[nt][2] * i1), rna(of[nt][3] * i1));
    }
}

// ---------------------------------------------------------------------------
// Launch
// ---------------------------------------------------------------------------
extern "C" void kernel_launch(void* const* d_in, const int* in_sizes, int n_in,
                              void* d_out, int out_size)
{
    const float* x     = (const float*)d_in[0];
    const float* wq    = (const float*)d_in[1];
    const float* wk    = (const float*)d_in[2];
    const float* wv    = (const float*)d_in[3];
    const float* wo    = (const float*)d_in[4];
    const float* bo    = (const float*)d_in[5];
    const float* w1    = (const float*)d_in[6];
    const float* b1    = (const float*)d_in[7];
    const float* w2    = (const float*)d_in[8];
    const float* b2    = (const float*)d_in[9];
    const float* gamma = (const float*)d_in[10];
    const float* beta  = (const float*)d_in[11];
    float* out = (float*)d_out;

    float *xn, *q, *k, *v, *at, *res, *y, *hb;
    float *wqr, *wkr, *wvr, *wor, *w1r, *w2r;
    cudaGetSymbolAddress((void**)&xn,  g_xn);
    cudaGetSymbolAddress((void**)&q,   g_q);
    cudaGetSymbolAddress((void**)&k,   g_k);
    cudaGetSymbolAddress((void**)&v,   g_v);
    cudaGetSymbolAddress((void**)&at,  g_at);
    cudaGetSymbolAddress((void**)&res, g_res);
    cudaGetSymbolAddress((void**)&y,   g_y);
    cudaGetSymbolAddress((void**)&hb,  g_h);
    cudaGetSymbolAddress((void**)&wqr, g_wq);
    cudaGetSymbolAddress((void**)&wkr, g_wk);
    cudaGetSymbolAddress((void**)&wvr, g_wv);
    cudaGetSymbolAddress((void**)&wor, g_wo);
    cudaGetSymbolAddress((void**)&w1r, g_w1);
    cudaGetSymbolAddress((void**)&w2r, g_w2);

    const dim3 gqkv(Ee / 128, Mrows / 128, 3);
    const dim3 g768(Ee / 128, Mrows / 128);
    const dim3 g3072(FFf / 128, Mrows / 128);

    cudaFuncSetAttribute(flash_mma, cudaFuncAttributeMaxDynamicSharedMemorySize, FSMEM);
    cudaFuncSetAttribute(gemm_mma<EPI_NONE,3,true>,       cudaFuncAttributeMaxDynamicSharedMemorySize, SMEMB);
    cudaFuncSetAttribute(gemm_mma<EPI_BIAS_RES,1,false>,  cudaFuncAttributeMaxDynamicSharedMemorySize, SMEMB);
    cudaFuncSetAttribute(gemm_mma<EPI_BIAS_GELU,1,true>,  cudaFuncAttributeMaxDynamicSharedMemorySize, SMEMB);

    round_all<<<ROUND_BLOCKS, 256>>>(wq, wk, wv, wo, w1, w2,
                                     wqr, wkr, wvr, wor, w1r, w2r);

    ln_kernel<<<Mrows, 256>>>(x, gamma, beta, xn);

    gemm_mma<EPI_NONE,3,true><<<gqkv, 512, SMEMB>>>(xn, wqr, wkr, wvr, nullptr, nullptr,
                                                    q, k, v, Mrows, Ee, Ee);

    flash_mma<<<dim3(Ss / 64, Hh, Bb), 128, FSMEM>>>(q, k, v, at);

    gemm_mma<EPI_BIAS_RES,1,false><<<g768, 512, SMEMB>>>(at, wor, wor, wor, bo, x,
                                                         res, res, res, Mrows, Ee, Ee);

    ln_kernel<<<Mrows, 256>>>(res, gamma, beta, y);

    gemm_mma<EPI_BIAS_GELU,1,true><<<g3072, 512, SMEMB>>>(y, w1r, w1r, w1r, b1, nullptr,
                                                          hb, hb, hb, Mrows, FFf, Ee);
    gemm_mma<EPI_BIAS_RES,1,false><<<g768, 512, SMEMB>>>(hb, w2r, w2r, w2r, b2, res,
                                                         out, out, out, Mrows, Ee, FFf);
}

// round 8
// speedup vs baseline: 1.3641x; 1.0034x over previous
#include <cuda_runtime.h>
#include <math.h>
#include <stdint.h>

// Problem constants
#define Bb   2
#define Ss   2048
#define Ee   768
#define Hh   12
#define Dd   64
#define FFf  3072
#define Mrows (Bb*Ss)   // 4096

// ---------------------------------------------------------------------------
// Scratch
// ---------------------------------------------------------------------------
__device__ float g_xn [Mrows*Ee];
__device__ float g_q  [Mrows*Ee];
__device__ float g_k  [Mrows*Ee];
__device__ float g_v  [Mrows*Ee];
__device__ float g_at [Mrows*Ee];
__device__ float g_res[Mrows*Ee];
__device__ float g_y  [Mrows*Ee];
__device__ float g_h  [Mrows*FFf];
__device__ float g_wq[Ee*Ee];
__device__ float g_wk[Ee*Ee];
__device__ float g_wv[Ee*Ee];
__device__ float g_wo[Ee*Ee];
__device__ float g_w1[FFf*Ee];
__device__ float g_w2[Ee*FFf];

// ---------------------------------------------------------------------------
// Helpers
// ---------------------------------------------------------------------------
__device__ __forceinline__ uint32_t smem_u32(const void* p) {
    uint32_t a;
    asm("{ .reg .u64 t; cvta.to.shared.u64 t, %1; cvt.u32.u64 %0, t; }"
        : "=r"(a) : "l"(p));
    return a;
}
__device__ __forceinline__ void cp16(uint32_t dst, const void* src) {
    asm volatile("cp.async.cg.shared.global [%0], [%1], 16;"
                 :: "r"(dst), "l"(src));
}
#define CP_COMMIT() asm volatile("cp.async.commit_group;" ::: "memory")
#define CP_WAIT(n)  asm volatile("cp.async.wait_group %0;" :: "n"(n) : "memory")

__device__ __forceinline__ float rna(float x) {
    uint32_t u;
    asm("cvt.rna.tf32.f32 %0, %1;" : "=r"(u) : "f"(x));
    return __uint_as_float(u);
}
__device__ __forceinline__ uint32_t fu(float x) { return __float_as_uint(x); }

__device__ __forceinline__ void mma_tf32(float* c, const uint32_t* a,
                                         uint32_t b0, uint32_t b1) {
    asm volatile(
        "mma.sync.aligned.m16n8k8.row.col.f32.tf32.tf32.f32 "
        "{%0,%1,%2,%3}, {%4,%5,%6,%7}, {%8,%9}, {%0,%1,%2,%3};"
        : "+f"(c[0]), "+f"(c[1]), "+f"(c[2]), "+f"(c[3])
        : "r"(a[0]), "r"(a[1]), "r"(a[2]), "r"(a[3]), "r"(b0), "r"(b1));
}

// ---------------------------------------------------------------------------
// Fused weight rounding (one launch)
// ---------------------------------------------------------------------------
__global__ void round_all(const float* __restrict__ wq, const float* __restrict__ wk,
                          const float* __restrict__ wv, const float* __restrict__ wo,
                          const float* __restrict__ w1, const float* __restrict__ w2,
                          float* __restrict__ dq, float* __restrict__ dk,
                          float* __restrict__ dv, float* __restrict__ dwo,
                          float* __restrict__ d1, float* __restrict__ d2)
{
    const int E4 = Ee * Ee / 4;
    const int F4 = (FFf * Ee) / 4;
    int i = blockIdx.x * blockDim.x + threadIdx.x;
    const float* s; float* d;
    if      (i < E4)          { s = wq; d = dq; }
    else if (i < 2*E4)        { s = wk; d = dk;  i -= E4; }
    else if (i < 3*E4)        { s = wv; d = dv;  i -= 2*E4; }
    else if (i < 4*E4)        { s = wo; d = dwo; i -= 3*E4; }
    else if (i < 4*E4 + F4)   { s = w1; d = d1;  i -= 4*E4; }
    else                      { s = w2; d = d2;  i -= 4*E4 + F4; }
    float4 v = ((const float4*)s)[i];
    v.x = rna(v.x); v.y = rna(v.y); v.z = rna(v.z); v.w = rna(v.w);
    ((float4*)d)[i] = v;
}
#define ROUND_BLOCKS ((4*(Ee*Ee/4) + 2*((FFf*Ee)/4)) / 256)

// ---------------------------------------------------------------------------
// LayerNorm (outputs rounded)
// ---------------------------------------------------------------------------
__global__ void ln_kernel(const float* __restrict__ X,
                          const float* __restrict__ gamma,
                          const float* __restrict__ beta,
                          float* __restrict__ Y)
{
    const int row = blockIdx.x;
    const float* x = X + (size_t)row * Ee;
    float*       y = Y + (size_t)row * Ee;
    const int t = threadIdx.x;

    float v0 = x[t], v1 = x[t + 256], v2 = x[t + 512];
    float s  = v0 + v1 + v2;

    __shared__ float red[8];
    #pragma unroll
    for (int off = 16; off; off >>= 1) s += __shfl_xor_sync(0xffffffffu, s, off);
    if ((t & 31) == 0) red[t >> 5] = s;
    __syncthreads();
    if (t < 8) {
        float r = red[t];
        #pragma unroll
        for (int off = 4; off; off >>= 1) r += __shfl_xor_sync(0xffu, r, off);
        if (t == 0) red[0] = r;
    }
    __syncthreads();
    const float mu = red[0] * (1.0f / Ee);
    __syncthreads();

    float d0 = v0 - mu, d1 = v1 - mu, d2 = v2 - mu;
    float q  = d0*d0 + d1*d1 + d2*d2;
    #pragma unroll
    for (int off = 16; off; off >>= 1) q += __shfl_xor_sync(0xffffffffu, q, off);
    if ((t & 31) == 0) red[t >> 5] = q;
    __syncthreads();
    if (t < 8) {
        float r = red[t];
        #pragma unroll
        for (int off = 4; off; off >>= 1) r += __shfl_xor_sync(0xffu, r, off);
        if (t == 0) red[0] = r;
    }
    __syncthreads();
    const float inv = rsqrtf(red[0] * (1.0f / Ee) + 1e-5f);

    y[t      ] = rna(d0 * inv * gamma[t      ] + beta[t      ]);
    y[t + 256] = rna(d1 * inv * gamma[t + 256] + beta[t + 256]);
    y[t + 512] = rna(d2 * inv * gamma[t + 512] + beta[t + 512]);
}

// ---------------------------------------------------------------------------
// tf32 GEMM: C = A * B^T (+ epilogue). CTA 128x128x64, 256 threads,
// 8 warps (4x2), warp tile 32x64. k-slot permutation: slot tg <-> k=4tg+e'
// so each thread's fragments for TWO k-steps come from ONE LDS.128.
// PITCH=80 (==16 mod 32) -> conflict-free LDS.128 phases. 2-stage cp.async.
// ---------------------------------------------------------------------------
enum { EPI_NONE = 0, EPI_BIAS = 1, EPI_BIAS_GELU = 2, EPI_BIAS_RES = 3 };

#define PITCH   80
#define TILEF   (128*PITCH)
#define STAGEB  (2*TILEF*4)
#define NSTAGE  2
#define SMEMB   (NSTAGE*STAGEB)     // 163840 B

template <int EPI, int NQKV, bool ROUT>
__global__ __launch_bounds__(256, 1)
void gemm_mma(const float* __restrict__ A,
              const float* __restrict__ Bq, const float* __restrict__ Bk,
              const float* __restrict__ Bv,
              const float* __restrict__ bias, const float* __restrict__ R,
              float* __restrict__ Cq, float* __restrict__ Ck,
              float* __restrict__ Cv,
              int M, int N, int K)
{
    const float* Bm = Bq;
    float*       C  = Cq;
    if (NQKV == 3) {
        if (blockIdx.z == 1)      { Bm = Bk; C = Ck; }
        else if (blockIdx.z == 2) { Bm = Bv; C = Cv; }
    }

    extern __shared__ float sm[];

    const int t    = threadIdx.x;
    const int lane = t & 31;
    const int wid  = t >> 5;
    const int wr   = wid & 3;
    const int wc   = wid >> 2;
    const int mr   = wr * 32;
    const int nc0  = wc * 64;
    const int g    = lane >> 2;
    const int tg   = lane & 3;
    const int r0   = t >> 4;
    const int c4   = t & 15;

    const int bm = blockIdx.y * 128;
    const int bn = blockIdx.x * 128;

    float c[2][8][4];
    #pragma unroll
    for (int mt = 0; mt < 2; mt++)
        #pragma unroll
        for (int nt = 0; nt < 8; nt++)
            #pragma unroll
            for (int i = 0; i < 4; i++) c[mt][nt][i] = 0.f;

    const uint32_t sBase = smem_u32(sm);

    auto issue = [&](int ci) {
        const int st = ci & 1;
        const int k0 = ci << 6;
        const uint32_t dA = sBase + (uint32_t)st * STAGEB;
        const uint32_t dB = dA + TILEF * 4;
        #pragma unroll
        for (int p = 0; p < 8; p++) {
            const int idx = p * 256 + t;
            const int row = idx >> 4;
            const int cc  = idx & 15;
            const uint32_t so = (uint32_t)(row * PITCH + cc * 4) * 4;
            cp16(dA + so, A  + (size_t)(bm + row) * K + k0 + cc * 4);
            cp16(dB + so, Bm + (size_t)(bn + row) * K + k0 + cc * 4);
        }
        CP_COMMIT();
    };

    const int nchunk = K >> 6;
    issue(0);

    #pragma unroll 1
    for (int ci = 0; ci < nchunk; ci++) {
        if (ci + 1 < nchunk) { issue(ci + 1); CP_WAIT(1); }
        else                 { CP_WAIT(0); }
        __syncthreads();

        const float* sa = sm + (ci & 1) * (2 * TILEF);
        const float* sb = sa + TILEF;

        #pragma unroll
        for (int kp = 0; kp < 4; kp++) {
            const int kb = kp * 16 + 4 * tg;
            float4 aq[2][2], bq[8];
            #pragma unroll
            for (int mt = 0; mt < 2; mt++) {
                aq[mt][0] = *(const float4*)(sa + (mr + mt*16 + g    ) * PITCH + kb);
                aq[mt][1] = *(const float4*)(sa + (mr + mt*16 + g + 8) * PITCH + kb);
            }
            #pragma unroll
            for (int nt = 0; nt < 8; nt++)
                bq[nt] = *(const float4*)(sb + (nc0 + nt*8 + g) * PITCH + kb);

            // even k-step: slots <- (x, y)
            {
                uint32_t a0[4] = { fu(aq[0][0].x), fu(aq[0][1].x),
                                   fu(aq[0][0].y), fu(aq[0][1].y) };
                uint32_t a1[4] = { fu(aq[1][0].x), fu(aq[1][1].x),
                                   fu(aq[1][0].y), fu(aq[1][1].y) };
                #pragma unroll
                for (int nt = 0; nt < 8; nt++) {
                    mma_tf32(c[0][nt], a0, fu(bq[nt].x), fu(bq[nt].y));
                    mma_tf32(c[1][nt], a1, fu(bq[nt].x), fu(bq[nt].y));
                }
            }
            // odd k-step: slots <- (z, w)
            {
                uint32_t a0[4] = { fu(aq[0][0].z), fu(aq[0][1].z),
                                   fu(aq[0][0].w), fu(aq[0][1].w) };
                uint32_t a1[4] = { fu(aq[1][0].z), fu(aq[1][1].z),
                                   fu(aq[1][0].w), fu(aq[1][1].w) };
                #pragma unroll
                for (int nt = 0; nt < 8; nt++) {
                    mma_tf32(c[0][nt], a0, fu(bq[nt].z), fu(bq[nt].w));
                    mma_tf32(c[1][nt], a1, fu(bq[nt].z), fu(bq[nt].w));
                }
            }
        }
        __syncthreads();
    }

    #pragma unroll
    for (int mt = 0; mt < 2; mt++) {
        #pragma unroll
        for (int half = 0; half < 2; half++) {
            const int row = bm + mr + mt * 16 + g + half * 8;
            #pragma unroll
            for (int nt = 0; nt < 8; nt++) {
                const int col = bn + nc0 + nt * 8 + 2 * tg;
                float2 v = make_float2(c[mt][nt][half * 2 + 0],
                                       c[mt][nt][half * 2 + 1]);
                if (EPI >= EPI_BIAS) {
                    float2 bb = *(const float2*)(bias + col);
                    v.x += bb.x; v.y += bb.y;
                }
                if (EPI == EPI_BIAS_GELU) {
                    v.x = 0.5f * v.x * (1.0f + erff(v.x * 0.70710678118654752f));
                    v.y = 0.5f * v.y * (1.0f + erff(v.y * 0.70710678118654752f));
                }
                if (EPI == EPI_BIAS_RES) {
                    float2 rr = *(const float2*)(R + (size_t)row * N + col);
                    v.x += rr.x; v.y += rr.y;
                }
                if (ROUT) { v.x = rna(v.x); v.y = rna(v.y); }
                *(float2*)(C + (size_t)row * N + col) = v;
            }
        }
    }
}

// ---------------------------------------------------------------------------
// Flash attention (tf32 mma): same k-slot permutation for QK^T and PV,
// cp.async double-buffered K/V, reversed qt order, PITCH 80.
// smem: Ks[2],Vs[2],Ps = 5 * 64*80 floats = 102400 B -> 2 CTAs/SM
// ---------------------------------------------------------------------------
#define FLDA 80
#define FT   (64*FLDA)
#define FSMEM (5*FT*4)

__global__ __launch_bounds__(128, 2)
void flash_mma(const float* __restrict__ Qg, const float* __restrict__ Kg,
               const float* __restrict__ Vg, float* __restrict__ Og)
{
    extern __shared__ float sm[];
    float* Ps = sm + 4 * FT;

    const int qt = (int)gridDim.x - 1 - (int)blockIdx.x;
    const int h = blockIdx.y, b = blockIdx.z;
    const int q0 = qt * 64;
    const int t = threadIdx.x, wid = t >> 5, lane = t & 31;
    const int g = lane >> 2, tg = lane & 3;
    const int r0l = wid * 16 + g;
    const size_t base = (size_t)b * Ss * Ee + h * Dd;
    const uint32_t sBase = smem_u32(sm);

    // stage Q into Ps, extract permuted register fragments
    #pragma unroll
    for (int p = 0; p < 8; p++) {
        const int idx = p * 128 + t, row = idx >> 4, c4 = idx & 15;
        *(float4*)&Ps[row * FLDA + c4 * 4] =
            *(const float4*)(Qg + base + (size_t)(q0 + row) * Ee + c4 * 4);
    }
    __syncthreads();
    float4 qA[4][2];
    #pragma unroll
    for (int kp = 0; kp < 4; kp++) {
        const int kb = kp * 16 + 4 * tg;
        qA[kp][0] = *(const float4*)&Ps[r0l * FLDA + kb];
        qA[kp][1] = *(const float4*)&Ps[(r0l + 8) * FLDA + kb];
    }

    auto issue = [&](int kt) {
        const int buf = kt & 1;
        const int k0 = kt * 64;
        const uint32_t dK = sBase + (uint32_t)buf * (2 * FT) * 4;
        const uint32_t dV = dK + FT * 4;
        #pragma unroll
        for (int p = 0; p < 8; p++) {
            const int idx = p * 128 + t, row = idx >> 4, c4 = idx & 15;
            const uint32_t so = (uint32_t)(row * FLDA + c4 * 4) * 4;
            cp16(dK + so, Kg + base + (size_t)(k0 + row) * Ee + c4 * 4);
            cp16(dV + so, Vg + base + (size_t)(k0 + row) * Ee + c4 * 4);
        }
        CP_COMMIT();
    };

    float m0 = -INFINITY, m1 = -INFINITY, l0 = 0.f, l1 = 0.f;
    float of[8][4];
    #pragma unroll
    for (int nt = 0; nt < 8; nt++) { of[nt][0]=of[nt][1]=of[nt][2]=of[nt][3]=0.f; }

    issue(0);

    for (int kt = 0; kt <= qt; kt++) {
        if (kt < qt) { issue(kt + 1); CP_WAIT(1); }
        else         { CP_WAIT(0); }
        __syncthreads();

        const float* Ks = sm + (kt & 1) * (2 * FT);
        const float* Vs = Ks + FT;

        // S = Q @ K^T (permuted slots; one LDS.128 per nt per k-pair)
        float cS[8][4];
        #pragma unroll
        for (int nt = 0; nt < 8; nt++) { cS[nt][0]=cS[nt][1]=cS[nt][2]=cS[nt][3]=0.f; }
        #pragma unroll
        for (int kp = 0; kp < 4; kp++) {
            const int kb = kp * 16 + 4 * tg;
            uint32_t ae[4] = { fu(qA[kp][0].x), fu(qA[kp][1].x),
                               fu(qA[kp][0].y), fu(qA[kp][1].y) };
            uint32_t ao[4] = { fu(qA[kp][0].z), fu(qA[kp][1].z),
                               fu(qA[kp][0].w), fu(qA[kp][1].w) };
            #pragma unroll
            for (int nt = 0; nt < 8; nt++) {
                float4 kb4 = *(const float4*)(Ks + (nt * 8 + g) * FLDA + kb);
                mma_tf32(cS[nt], ae, fu(kb4.x), fu(kb4.y));
                mma_tf32(cS[nt], ao, fu(kb4.z), fu(kb4.w));
            }
        }

        // fp32 online softmax
        const bool diag = (kt == qt);
        float mx0 = -INFINITY, mx1 = -INFINITY;
        #pragma unroll
        for (int nt = 0; nt < 8; nt++) {
            float v0 = cS[nt][0] * 0.125f, v1 = cS[nt][1] * 0.125f;
            float v2 = cS[nt][2] * 0.125f, v3 = cS[nt][3] * 0.125f;
            if (diag) {
                const int j0 = nt * 8 + 2 * tg;
                if (j0     > r0l)     v0 = -1e30f;
                if (j0 + 1 > r0l)     v1 = -1e30f;
                if (j0     > r0l + 8) v2 = -1e30f;
                if (j0 + 1 > r0l + 8) v3 = -1e30f;
            }
            cS[nt][0] = v0; cS[nt][1] = v1; cS[nt][2] = v2; cS[nt][3] = v3;
            mx0 = fmaxf(mx0, fmaxf(v0, v1));
            mx1 = fmaxf(mx1, fmaxf(v2, v3));
        }
        mx0 = fmaxf(mx0, __shfl_xor_sync(0xffffffffu, mx0, 1));
        mx0 = fmaxf(mx0, __shfl_xor_sync(0xffffffffu, mx0, 2));
        mx1 = fmaxf(mx1, __shfl_xor_sync(0xffffffffu, mx1, 1));
        mx1 = fmaxf(mx1, __shfl_xor_sync(0xffffffffu, mx1, 2));
        const float mn0 = fmaxf(m0, mx0), mn1 = fmaxf(m1, mx1);
        const float a0 = __expf(m0 - mn0), a1 = __expf(m1 - mn1);
        float rs0 = 0.f, rs1 = 0.f;
        #pragma unroll
        for (int nt = 0; nt < 8; nt++) {
            const float p0e = __expf(cS[nt][0] - mn0);
            const float p1e = __expf(cS[nt][1] - mn0);
            const float p2e = __expf(cS[nt][2] - mn1);
            const float p3e = __expf(cS[nt][3] - mn1);
            cS[nt][0] = p0e; cS[nt][1] = p1e; cS[nt][2] = p2e; cS[nt][3] = p3e;
            rs0 += p0e + p1e; rs1 += p2e + p3e;
        }
        rs0 += __shfl_xor_sync(0xffffffffu, rs0, 1);
        rs0 += __shfl_xor_sync(0xffffffffu, rs0, 2);
        rs1 += __shfl_xor_sync(0xffffffffu, rs1, 1);
        rs1 += __shfl_xor_sync(0xffffffffu, rs1, 2);
        l0 = l0 * a0 + rs0; l1 = l1 * a1 + rs1;
        m0 = mn0; m1 = mn1;
        #pragma unroll
        for (int nt = 0; nt < 8; nt++) {
            of[nt][0] *= a0; of[nt][1] *= a0;
            of[nt][2] *= a1; of[nt][3] *= a1;
        }

        // P round-trip through smem
        #pragma unroll
        for (int nt = 0; nt < 8; nt++) {
            *(float2*)&Ps[r0l * FLDA + nt * 8 + 2 * tg] =
                make_float2(rna(cS[nt][0]), rna(cS[nt][1]));
            *(float2*)&Ps[(r0l + 8) * FLDA + nt * 8 + 2 * tg] =
                make_float2(rna(cS[nt][2]), rna(cS[nt][3]));
        }
        __syncthreads();

        // O += P @ V (permuted slots; V rows broadcast per quad)
        #pragma unroll
        for (int kp = 0; kp < 4; kp++) {
            const int kb = kp * 16 + 4 * tg;
            float4 p0 = *(const float4*)&Ps[r0l * FLDA + kb];
            float4 p1 = *(const float4*)&Ps[(r0l + 8) * FLDA + kb];
            uint32_t pe[4] = { fu(p0.x), fu(p1.x), fu(p0.y), fu(p1.y) };
            uint32_t po[4] = { fu(p0.z), fu(p1.z), fu(p0.w), fu(p1.w) };
            const float* vr = Vs + kb * FLDA + g;   // rows kb..kb+3
            #pragma unroll
            for (int nt = 0; nt < 8; nt++) {
                const float* vn = vr + nt * 8;
                mma_tf32(of[nt], pe, fu(vn[0]),        fu(vn[FLDA]));
                mma_tf32(of[nt], po, fu(vn[2 * FLDA]), fu(vn[3 * FLDA]));
            }
        }
        __syncthreads();
    }

    const float i0 = 1.f / l0, i1 = 1.f / l1;
    #pragma unroll
    for (int nt = 0; nt < 8; nt++) {
        const int col = nt * 8 + 2 * tg;
        float* o0 = Og + base + (size_t)(q0 + r0l) * Ee + col;
        float* o1 = o0 + 8 * Ee;
        *(float2*)o0 = make_float2(rna(of[nt][0] * i0), rna(of[nt][1] * i0));
        *(float2*)o1 = make_float2(rna(of[nt][2] * i1), rna(of[nt][3] * i1));
    }
}

// ---------------------------------------------------------------------------
// Launch
// ---------------------------------------------------------------------------
extern "C" void kernel_launch(void* const* d_in, const int* in_sizes, int n_in,
                              void* d_out, int out_size)
{
    const float* x     = (const float*)d_in[0];
    const float* wq    = (const float*)d_in[1];
    const float* wk    = (const float*)d_in[2];
    const float* wv    = (const float*)d_in[3];
    const float* wo    = (const float*)d_in[4];
    const float* bo    = (const float*)d_in[5];
    const float* w1    = (const float*)d_in[6];
    const float* b1    = (const float*)d_in[7];
    const float* w2    = (const float*)d_in[8];
    const float* b2    = (const float*)d_in[9];
    const float* gamma = (const float*)d_in[10];
    const float* beta  = (const float*)d_in[11];
    float* out = (float*)d_out;

    float *xn, *q, *k, *v, *at, *res, *y, *hb;
    float *wqr, *wkr, *wvr, *wor, *w1r, *w2r;
    cudaGetSymbolAddress((void**)&xn,  g_xn);
    cudaGetSymbolAddress((void**)&q,   g_q);
    cudaGetSymbolAddress((void**)&k,   g_k);
    cudaGetSymbolAddress((void**)&v,   g_v);
    cudaGetSymbolAddress((void**)&at,  g_at);
    cudaGetSymbolAddress((void**)&res, g_res);
    cudaGetSymbolAddress((void**)&y,   g_y);
    cudaGetSymbolAddress((void**)&hb,  g_h);
    cudaGetSymbolAddress((void**)&wqr, g_wq);
    cudaGetSymbolAddress((void**)&wkr, g_wk);
    cudaGetSymbolAddress((void**)&wvr, g_wv);
    cudaGetSymbolAddress((void**)&wor, g_wo);
    cudaGetSymbolAddress((void**)&w1r, g_w1);
    cudaGetSymbolAddress((void**)&w2r, g_w2);

    const dim3 gqkv(Ee / 128, Mrows / 128, 3);
    const dim3 g768(Ee / 128, Mrows / 128);
    const dim3 g3072(FFf / 128, Mrows / 128);

    cudaFuncSetAttribute(flash_mma, cudaFuncAttributeMaxDynamicSharedMemorySize, FSMEM);
    cudaFuncSetAttribute(gemm_mma<EPI_NONE,3,true>,       cudaFuncAttributeMaxDynamicSharedMemorySize, SMEMB);
    cudaFuncSetAttribute(gemm_mma<EPI_BIAS_RES,1,false>,  cudaFuncAttributeMaxDynamicSharedMemorySize, SMEMB);
    cudaFuncSetAttribute(gemm_mma<EPI_BIAS_GELU,1,true>,  cudaFuncAttributeMaxDynamicSharedMemorySize, SMEMB);

    round_all<<<ROUND_BLOCKS, 256>>>(wq, wk, wv, wo, w1, w2,
                                     wqr, wkr, wvr, wor, w1r, w2r);

    ln_kernel<<<Mrows, 256>>>(x, gamma, beta, xn);

    gemm_mma<EPI_NONE,3,true><<<gqkv, 256, SMEMB>>>(xn, wqr, wkr, wvr, nullptr, nullptr,
                                                    q, k, v, Mrows, Ee, Ee);

    flash_mma<<<dim3(Ss / 64, Hh, Bb), 128, FSMEM>>>(q, k, v, at);

    gemm_mma<EPI_BIAS_RES,1,false><<<g768, 256, SMEMB>>>(at, wor, wor, wor, bo, x,
                                                         res, res, res, Mrows, Ee, Ee);

    ln_kernel<<<Mrows, 256>>>(res, gamma, beta, y);

    gemm_mma<EPI_BIAS_GELU,1,true><<<g3072, 256, SMEMB>>>(y, w1r, w1r, w1r, b1, nullptr,
                                                          hb, hb, hb, Mrows, FFf, Ee);
    gemm_mma<EPI_BIAS_RES,1,false><<<g768, 256, SMEMB>>>(hb, w2r, w2r, w2r, b2, res,
                                                         out, out, out, Mrows, Ee, FFf);
}

// round 9
// speedup vs baseline: 1.4290x; 1.0476x over previous
#include <cuda_runtime.h>
#include <math.h>
#include <stdint.h>

// Problem constants
#define Bb   2
#define Ss   2048
#define Ee   768
#define Hh   12
#define Dd   64
#define FFf  3072
#define Mrows (Bb*Ss)   // 4096

// ---------------------------------------------------------------------------
// Scratch
// ---------------------------------------------------------------------------
__device__ float g_xn [Mrows*Ee];
__device__ float g_q  [Mrows*Ee];
__device__ float g_k  [Mrows*Ee];
__device__ float g_v  [Mrows*Ee];
__device__ float g_at [Mrows*Ee];
__device__ float g_res[Mrows*Ee];
__device__ float g_y  [Mrows*Ee];
__device__ float g_h  [Mrows*FFf];
__device__ float g_wq[Ee*Ee];
__device__ float g_wk[Ee*Ee];
__device__ float g_wv[Ee*Ee];
__device__ float g_wo[Ee*Ee];
__device__ float g_w1[FFf*Ee];
__device__ float g_w2[Ee*FFf];

// ---------------------------------------------------------------------------
// Helpers
// ---------------------------------------------------------------------------
__device__ __forceinline__ uint32_t smem_u32(const void* p) {
    uint32_t a;
    asm("{ .reg .u64 t; cvta.to.shared.u64 t, %1; cvt.u32.u64 %0, t; }"
        : "=r"(a) : "l"(p));
    return a;
}
__device__ __forceinline__ void cp16(uint32_t dst, const void* src) {
    asm volatile("cp.async.cg.shared.global [%0], [%1], 16;"
                 :: "r"(dst), "l"(src));
}
#define CP_COMMIT() asm volatile("cp.async.commit_group;" ::: "memory")
#define CP_WAIT(n)  asm volatile("cp.async.wait_group %0;" :: "n"(n) : "memory")

__device__ __forceinline__ float rna(float x) {
    uint32_t u;
    asm("cvt.rna.tf32.f32 %0, %1;" : "=r"(u) : "f"(x));
    return __uint_as_float(u);
}
__device__ __forceinline__ uint32_t fu(float x) { return __float_as_uint(x); }

__device__ __forceinline__ void mma_tf32(float* c, const uint32_t* a,
                                         uint32_t b0, uint32_t b1) {
    asm volatile(
        "mma.sync.aligned.m16n8k8.row.col.f32.tf32.tf32.f32 "
        "{%0,%1,%2,%3}, {%4,%5,%6,%7}, {%8,%9}, {%0,%1,%2,%3};"
        : "+f"(c[0]), "+f"(c[1]), "+f"(c[2]), "+f"(c[3])
        : "r"(a[0]), "r"(a[1]), "r"(a[2]), "r"(a[3]), "r"(b0), "r"(b1));
}

// ---------------------------------------------------------------------------
// Fused weight rounding (one launch)
// ---------------------------------------------------------------------------
__global__ void round_all(const float* __restrict__ wq, const float* __restrict__ wk,
                          const float* __restrict__ wv, const float* __restrict__ wo,
                          const float* __restrict__ w1, const float* __restrict__ w2,
                          float* __restrict__ dq, float* __restrict__ dk,
                          float* __restrict__ dv, float* __restrict__ dwo,
                          float* __restrict__ d1, float* __restrict__ d2)
{
    const int E4 = Ee * Ee / 4;
    const int F4 = (FFf * Ee) / 4;
    int i = blockIdx.x * blockDim.x + threadIdx.x;
    const float* s; float* d;
    if      (i < E4)          { s = wq; d = dq; }
    else if (i < 2*E4)        { s = wk; d = dk;  i -= E4; }
    else if (i < 3*E4)        { s = wv; d = dv;  i -= 2*E4; }
    else if (i < 4*E4)        { s = wo; d = dwo; i -= 3*E4; }
    else if (i < 4*E4 + F4)   { s = w1; d = d1;  i -= 4*E4; }
    else                      { s = w2; d = d2;  i -= 4*E4 + F4; }
    float4 v = ((const float4*)s)[i];
    v.x = rna(v.x); v.y = rna(v.y); v.z = rna(v.z); v.w = rna(v.w);
    ((float4*)d)[i] = v;
}
#define ROUND_BLOCKS ((4*(Ee*Ee/4) + 2*((FFf*Ee)/4)) / 256)

// ---------------------------------------------------------------------------
// LayerNorm (outputs rounded)
// ---------------------------------------------------------------------------
__global__ void ln_kernel(const float* __restrict__ X,
                          const float* __restrict__ gamma,
                          const float* __restrict__ beta,
                          float* __restrict__ Y)
{
    const int row = blockIdx.x;
    const float* x = X + (size_t)row * Ee;
    float*       y = Y + (size_t)row * Ee;
    const int t = threadIdx.x;

    float v0 = x[t], v1 = x[t + 256], v2 = x[t + 512];
    float s  = v0 + v1 + v2;

    __shared__ float red[8];
    #pragma unroll
    for (int off = 16; off; off >>= 1) s += __shfl_xor_sync(0xffffffffu, s, off);
    if ((t & 31) == 0) red[t >> 5] = s;
    __syncthreads();
    if (t < 8) {
        float r = red[t];
        #pragma unroll
        for (int off = 4; off; off >>= 1) r += __shfl_xor_sync(0xffu, r, off);
        if (t == 0) red[0] = r;
    }
    __syncthreads();
    const float mu = red[0] * (1.0f / Ee);
    __syncthreads();

    float d0 = v0 - mu, d1 = v1 - mu, d2 = v2 - mu;
    float q  = d0*d0 + d1*d1 + d2*d2;
    #pragma unroll
    for (int off = 16; off; off >>= 1) q += __shfl_xor_sync(0xffffffffu, q, off);
    if ((t & 31) == 0) red[t >> 5] = q;
    __syncthreads();
    if (t < 8) {
        float r = red[t];
        #pragma unroll
        for (int off = 4; off; off >>= 1) r += __shfl_xor_sync(0xffu, r, off);
        if (t == 0) red[0] = r;
    }
    __syncthreads();
    const float inv = rsqrtf(red[0] * (1.0f / Ee) + 1e-5f);

    y[t      ] = rna(d0 * inv * gamma[t      ] + beta[t      ]);
    y[t + 256] = rna(d1 * inv * gamma[t + 256] + beta[t + 256]);
    y[t + 512] = rna(d2 * inv * gamma[t + 512] + beta[t + 512]);
}

// ---------------------------------------------------------------------------
// tf32 GEMM (R8 version, kept): CTA 128x128x64, 256 threads, 8 warps (4x2),
// warp tile 32x64, k-slot permutation -> LDS.128 fragment loads, PITCH 80,
// 2-stage cp.async.
// ---------------------------------------------------------------------------
enum { EPI_NONE = 0, EPI_BIAS = 1, EPI_BIAS_GELU = 2, EPI_BIAS_RES = 3 };

#define PITCH   80
#define TILEF   (128*PITCH)
#define STAGEB  (2*TILEF*4)
#define NSTAGE  2
#define SMEMB   (NSTAGE*STAGEB)     // 163840 B

template <int EPI, int NQKV, bool ROUT>
__global__ __launch_bounds__(256, 1)
void gemm_mma(const float* __restrict__ A,
              const float* __restrict__ Bq, const float* __restrict__ Bk,
              const float* __restrict__ Bv,
              const float* __restrict__ bias, const float* __restrict__ R,
              float* __restrict__ Cq, float* __restrict__ Ck,
              float* __restrict__ Cv,
              int M, int N, int K)
{
    const float* Bm = Bq;
    float*       C  = Cq;
    if (NQKV == 3) {
        if (blockIdx.z == 1)      { Bm = Bk; C = Ck; }
        else if (blockIdx.z == 2) { Bm = Bv; C = Cv; }
    }

    extern __shared__ float sm[];

    const int t    = threadIdx.x;
    const int lane = t & 31;
    const int wid  = t >> 5;
    const int wr   = wid & 3;
    const int wc   = wid >> 2;
    const int mr   = wr * 32;
    const int nc0  = wc * 64;
    const int g    = lane >> 2;
    const int tg   = lane & 3;

    const int bm = blockIdx.y * 128;
    const int bn = blockIdx.x * 128;

    float c[2][8][4];
    #pragma unroll
    for (int mt = 0; mt < 2; mt++)
        #pragma unroll
        for (int nt = 0; nt < 8; nt++)
            #pragma unroll
            for (int i = 0; i < 4; i++) c[mt][nt][i] = 0.f;

    const uint32_t sBase = smem_u32(sm);

    auto issue = [&](int ci) {
        const int st = ci & 1;
        const int k0 = ci << 6;
        const uint32_t dA = sBase + (uint32_t)st * STAGEB;
        const uint32_t dB = dA + TILEF * 4;
        #pragma unroll
        for (int p = 0; p < 8; p++) {
            const int idx = p * 256 + t;
            const int row = idx >> 4;
            const int cc  = idx & 15;
            const uint32_t so = (uint32_t)(row * PITCH + cc * 4) * 4;
            cp16(dA + so, A  + (size_t)(bm + row) * K + k0 + cc * 4);
            cp16(dB + so, Bm + (size_t)(bn + row) * K + k0 + cc * 4);
        }
        CP_COMMIT();
    };

    const int nchunk = K >> 6;
    issue(0);

    #pragma unroll 1
    for (int ci = 0; ci < nchunk; ci++) {
        if (ci + 1 < nchunk) { issue(ci + 1); CP_WAIT(1); }
        else                 { CP_WAIT(0); }
        __syncthreads();

        const float* sa = sm + (ci & 1) * (2 * TILEF);
        const float* sb = sa + TILEF;

        #pragma unroll
        for (int kp = 0; kp < 4; kp++) {
            const int kb = kp * 16 + 4 * tg;
            float4 aq[2][2], bq[8];
            #pragma unroll
            for (int mt = 0; mt < 2; mt++) {
                aq[mt][0] = *(const float4*)(sa + (mr + mt*16 + g    ) * PITCH + kb);
                aq[mt][1] = *(const float4*)(sa + (mr + mt*16 + g + 8) * PITCH + kb);
            }
            #pragma unroll
            for (int nt = 0; nt < 8; nt++)
                bq[nt] = *(const float4*)(sb + (nc0 + nt*8 + g) * PITCH + kb);

            // even k-step: slots <- (x, y)
            {
                uint32_t a0[4] = { fu(aq[0][0].x), fu(aq[0][1].x),
                                   fu(aq[0][0].y), fu(aq[0][1].y) };
                uint32_t a1[4] = { fu(aq[1][0].x), fu(aq[1][1].x),
                                   fu(aq[1][0].y), fu(aq[1][1].y) };
                #pragma unroll
                for (int nt = 0; nt < 8; nt++) {
                    mma_tf32(c[0][nt], a0, fu(bq[nt].x), fu(bq[nt].y));
                    mma_tf32(c[1][nt], a1, fu(bq[nt].x), fu(bq[nt].y));
                }
            }
            // odd k-step: slots <- (z, w)
            {
                uint32_t a0[4] = { fu(aq[0][0].z), fu(aq[0][1].z),
                                   fu(aq[0][0].w), fu(aq[0][1].w) };
                uint32_t a1[4] = { fu(aq[1][0].z), fu(aq[1][1].z),
                                   fu(aq[1][0].w), fu(aq[1][1].w) };
                #pragma unroll
                for (int nt = 0; nt < 8; nt++) {
                    mma_tf32(c[0][nt], a0, fu(bq[nt].z), fu(bq[nt].w));
                    mma_tf32(c[1][nt], a1, fu(bq[nt].z), fu(bq[nt].w));
                }
            }
        }
        __syncthreads();
    }

    #pragma unroll
    for (int mt = 0; mt < 2; mt++) {
        #pragma unroll
        for (int half = 0; half < 2; half++) {
            const int row = bm + mr + mt * 16 + g + half * 8;
            #pragma unroll
            for (int nt = 0; nt < 8; nt++) {
                const int col = bn + nc0 + nt * 8 + 2 * tg;
                float2 v = make_float2(c[mt][nt][half * 2 + 0],
                                       c[mt][nt][half * 2 + 1]);
                if (EPI >= EPI_BIAS) {
                    float2 bb = *(const float2*)(bias + col);
                    v.x += bb.x; v.y += bb.y;
                }
                if (EPI == EPI_BIAS_GELU) {
                    v.x = 0.5f * v.x * (1.0f + erff(v.x * 0.70710678118654752f));
                    v.y = 0.5f * v.y * (1.0f + erff(v.y * 0.70710678118654752f));
                }
                if (EPI == EPI_BIAS_RES) {
                    float2 rr = *(const float2*)(R + (size_t)row * N + col);
                    v.x += rr.x; v.y += rr.y;
                }
                if (ROUT) { v.x = rna(v.x); v.y = rna(v.y); }
                *(float2*)(C + (size_t)row * N + col) = v;
            }
        }
    }
}

// ---------------------------------------------------------------------------
// Flash attention (R7 version, reverted): tf32 mma, V row-major,
// cp.async double-buffered K/V, reversed qt order, FLDA 68.
// smem: Ks[2],Vs[2],Ps = 5 * 64*68 floats = 87040 B -> 2 CTAs/SM
// ---------------------------------------------------------------------------
#define FLDA 68
#define FT   (64*FLDA)
#define FSMEM (5*FT*4)

__global__ __launch_bounds__(128, 2)
void flash_mma(const float* __restrict__ Qg, const float* __restrict__ Kg,
               const float* __restrict__ Vg, float* __restrict__ Og)
{
    extern __shared__ float sm[];
    float* Ps = sm + 4 * FT;

    const int qt = (int)gridDim.x - 1 - (int)blockIdx.x;   // biggest first
    const int h = blockIdx.y, b = blockIdx.z;
    const int q0 = qt * 64;
    const int t = threadIdx.x, wid = t >> 5, lane = t & 31;
    const int g = lane >> 2, tg = lane & 3;
    const int r0l = wid * 16 + g;
    const size_t base = (size_t)b * Ss * Ee + h * Dd;
    const uint32_t sBase = smem_u32(sm);

    // stage Q into Ps, extract register fragments
    #pragma unroll
    for (int p = 0; p < 8; p++) {
        const int idx = p * 128 + t, row = idx >> 4, c4 = idx & 15;
        *(float4*)&Ps[row * FLDA + c4 * 4] =
            *(const float4*)(Qg + base + (size_t)(q0 + row) * Ee + c4 * 4);
    }
    __syncthreads();
    uint32_t qf[8][4];
    #pragma unroll
    for (int kk = 0; kk < 8; kk++) {
        const float* p0 = Ps + r0l * FLDA + kk * 8 + tg;
        qf[kk][0] = __float_as_uint(p0[0]);
        qf[kk][1] = __float_as_uint(p0[8 * FLDA]);
        qf[kk][2] = __float_as_uint(p0[4]);
        qf[kk][3] = __float_as_uint(p0[8 * FLDA + 4]);
    }

    // K/V staging via cp.async (double buffered)
    auto issue = [&](int kt) {
        const int buf = kt & 1;
        const int k0 = kt * 64;
        const uint32_t dK = sBase + (uint32_t)buf * (2 * FT) * 4;
        const uint32_t dV = dK + FT * 4;
        #pragma unroll
        for (int p = 0; p < 8; p++) {
            const int idx = p * 128 + t, row = idx >> 4, c4 = idx & 15;
            const uint32_t so = (uint32_t)(row * FLDA + c4 * 4) * 4;
            cp16(dK + so, Kg + base + (size_t)(k0 + row) * Ee + c4 * 4);
            cp16(dV + so, Vg + base + (size_t)(k0 + row) * Ee + c4 * 4);
        }
        CP_COMMIT();
    };

    float m0 = -INFINITY, m1 = -INFINITY, l0 = 0.f, l1 = 0.f;
    float of[8][4];
    #pragma unroll
    for (int nt = 0; nt < 8; nt++) { of[nt][0]=of[nt][1]=of[nt][2]=of[nt][3]=0.f; }

    issue(0);

    for (int kt = 0; kt <= qt; kt++) {
        if (kt < qt) { issue(kt + 1); CP_WAIT(1); }
        else         { CP_WAIT(0); }
        __syncthreads();

        const float* Ks = sm + (kt & 1) * (2 * FT);
        const float* Vs = Ks + FT;

        // S = Q @ K^T
        float cS[8][4];
        #pragma unroll
        for (int nt = 0; nt < 8; nt++) { cS[nt][0]=cS[nt][1]=cS[nt][2]=cS[nt][3]=0.f; }
        #pragma unroll
        for (int kk = 0; kk < 8; kk++) {
            #pragma unroll
            for (int nt = 0; nt < 8; nt++) {
                const float* bp = Ks + (nt * 8 + g) * FLDA + kk * 8 + tg;
                mma_tf32(cS[nt], qf[kk],
                         __float_as_uint(bp[0]), __float_as_uint(bp[4]));
            }
        }

        // fp32 online softmax
        const bool diag = (kt == qt);
        float mx0 = -INFINITY, mx1 = -INFINITY;
        #pragma unroll
        for (int nt = 0; nt < 8; nt++) {
            float v0 = cS[nt][0] * 0.125f, v1 = cS[nt][1] * 0.125f;
            float v2 = cS[nt][2] * 0.125f, v3 = cS[nt][3] * 0.125f;
            if (diag) {
                const int j0 = nt * 8 + 2 * tg;
                if (j0     > r0l)     v0 = -1e30f;
                if (j0 + 1 > r0l)     v1 = -1e30f;
                if (j0     > r0l + 8) v2 = -1e30f;
                if (j0 + 1 > r0l + 8) v3 = -1e30f;
            }
            cS[nt][0] = v0; cS[nt][1] = v1; cS[nt][2] = v2; cS[nt][3] = v3;
            mx0 = fmaxf(mx0, fmaxf(v0, v1));
            mx1 = fmaxf(mx1, fmaxf(v2, v3));
        }
        mx0 = fmaxf(mx0, __shfl_xor_sync(0xffffffffu, mx0, 1));
        mx0 = fmaxf(mx0, __shfl_xor_sync(0xffffffffu, mx0, 2));
        mx1 = fmaxf(mx1, __shfl_xor_sync(0xffffffffu, mx1, 1));
        mx1 = fmaxf(mx1, __shfl_xor_sync(0xffffffffu, mx1, 2));
        const float mn0 = fmaxf(m0, mx0), mn1 = fmaxf(m1, mx1);
        const float a0 = __expf(m0 - mn0), a1 = __expf(m1 - mn1);
        float rs0 = 0.f, rs1 = 0.f;
        #pragma unroll
        for (int nt = 0; nt < 8; nt++) {
            const float p0e = __expf(cS[nt][0] - mn0);
            const float p1e = __expf(cS[nt][1] - mn0);
            const float p2e = __expf(cS[nt][2] - mn1);
            const float p3e = __expf(cS[nt][3] - mn1);
            cS[nt][0] = p0e; cS[nt][1] = p1e; cS[nt][2] = p2e; cS[nt][3] = p3e;
            rs0 += p0e + p1e; rs1 += p2e + p3e;
        }
        rs0 += __shfl_xor_sync(0xffffffffu, rs0, 1);
        rs0 += __shfl_xor_sync(0xffffffffu, rs0, 2);
        rs1 += __shfl_xor_sync(0xffffffffu, rs1, 1);
        rs1 += __shfl_xor_sync(0xffffffffu, rs1, 2);
        l0 = l0 * a0 + rs0; l1 = l1 * a1 + rs1;
        m0 = mn0; m1 = mn1;
        #pragma unroll
        for (int nt = 0; nt < 8; nt++) {
            of[nt][0] *= a0; of[nt][1] *= a0;
            of[nt][2] *= a1; of[nt][3] *= a1;
        }

        // P round-trip through smem (C->A fragment layout)
        #pragma unroll
        for (int nt = 0; nt < 8; nt++) {
            *(float2*)&Ps[r0l * FLDA + nt * 8 + 2 * tg] =
                make_float2(rna(cS[nt][0]), rna(cS[nt][1]));
            *(float2*)&Ps[(r0l + 8) * FLDA + nt * 8 + 2 * tg] =
                make_float2(rna(cS[nt][2]), rna(cS[nt][3]));
        }
        __syncthreads();

        // O += P @ V   (V row-major: B[k][n] = Vs[k*FLDA + n])
        #pragma unroll
        for (int kk = 0; kk < 8; kk++) {
            const float* pp = Ps + r0l * FLDA + kk * 8 + tg;
            uint32_t pa[4];
            pa[0] = __float_as_uint(pp[0]);
            pa[1] = __float_as_uint(pp[8 * FLDA]);
            pa[2] = __float_as_uint(pp[4]);
            pa[3] = __float_as_uint(pp[8 * FLDA + 4]);
            const float* vrow0 = Vs + (kk * 8 + tg) * FLDA;
            const float* vrow1 = vrow0 + 4 * FLDA;
            #pragma unroll
            for (int nt = 0; nt < 8; nt++) {
                mma_tf32(of[nt], pa,
                         __float_as_uint(vrow0[nt * 8 + g]),
                         __float_as_uint(vrow1[nt * 8 + g]));
            }
        }
        __syncthreads();
    }

    const float i0 = 1.f / l0, i1 = 1.f / l1;
    #pragma unroll
    for (int nt = 0; nt < 8; nt++) {
        const int col = nt * 8 + 2 * tg;
        float* o0 = Og + base + (size_t)(q0 + r0l) * Ee + col;
        float* o1 = o0 + 8 * Ee;
        *(float2*)o0 = make_float2(rna(of[nt][0] * i0), rna(of[nt][1] * i0));
        *(float2*)o1 = make_float2(rna(of[nt][2] * i1), rna(of[nt][3] * i1));
    }
}

// ---------------------------------------------------------------------------
// Launch
// ---------------------------------------------------------------------------
extern "C" void kernel_launch(void* const* d_in, const int* in_sizes, int n_in,
                              void* d_out, int out_size)
{
    const float* x     = (const float*)d_in[0];
    const float* wq    = (const float*)d_in[1];
    const float* wk    = (const float*)d_in[2];
    const float* wv    = (const float*)d_in[3];
    const float* wo    = (const float*)d_in[4];
    const float* bo    = (const float*)d_in[5];
    const float* w1    = (const float*)d_in[6];
    const float* b1    = (const float*)d_in[7];
    const float* w2    = (const float*)d_in[8];
    const float* b2    = (const float*)d_in[9];
    const float* gamma = (const float*)d_in[10];
    const float* beta  = (const float*)d_in[11];
    float* out = (float*)d_out;

    float *xn, *q, *k, *v, *at, *res, *y, *hb;
    float *wqr, *wkr, *wvr, *wor, *w1r, *w2r;
    cudaGetSymbolAddress((void**)&xn,  g_xn);
    cudaGetSymbolAddress((void**)&q,   g_q);
    cudaGetSymbolAddress((void**)&k,   g_k);
    cudaGetSymbolAddress((void**)&v,   g_v);
    cudaGetSymbolAddress((void**)&at,  g_at);
    cudaGetSymbolAddress((void**)&res, g_res);
    cudaGetSymbolAddress((void**)&y,   g_y);
    cudaGetSymbolAddress((void**)&hb,  g_h);
    cudaGetSymbolAddress((void**)&wqr, g_wq);
    cudaGetSymbolAddress((void**)&wkr, g_wk);
    cudaGetSymbolAddress((void**)&wvr, g_wv);
    cudaGetSymbolAddress((void**)&wor, g_wo);
    cudaGetSymbolAddress((void**)&w1r, g_w1);
    cudaGetSymbolAddress((void**)&w2r, g_w2);

    const dim3 gqkv(Ee / 128, Mrows / 128, 3);
    const dim3 g768(Ee / 128, Mrows / 128);
    const dim3 g3072(FFf / 128, Mrows / 128);

    cudaFuncSetAttribute(flash_mma, cudaFuncAttributeMaxDynamicSharedMemorySize, FSMEM);
    cudaFuncSetAttribute(gemm_mma<EPI_NONE,3,true>,       cudaFuncAttributeMaxDynamicSharedMemorySize, SMEMB);
    cudaFuncSetAttribute(gemm_mma<EPI_BIAS_RES,1,false>,  cudaFuncAttributeMaxDynamicSharedMemorySize, SMEMB);
    cudaFuncSetAttribute(gemm_mma<EPI_BIAS_GELU,1,true>,  cudaFuncAttributeMaxDynamicSharedMemorySize, SMEMB);

    round_all<<<ROUND_BLOCKS, 256>>>(wq, wk, wv, wo, w1, w2,
                                     wqr, wkr, wvr, wor, w1r, w2r);

    ln_kernel<<<Mrows, 256>>>(x, gamma, beta, xn);

    gemm_mma<EPI_NONE,3,true><<<gqkv, 256, SMEMB>>>(xn, wqr, wkr, wvr, nullptr, nullptr,
                                                    q, k, v, Mrows, Ee, Ee);

    flash_mma<<<dim3(Ss / 64, Hh, Bb), 128, FSMEM>>>(q, k, v, at);

    gemm_mma<EPI_BIAS_RES,1,false><<<g768, 256, SMEMB>>>(at, wor, wor, wor, bo, x,
                                                         res, res, res, Mrows, Ee, Ee);

    ln_kernel<<<Mrows, 256>>>(res, gamma, beta, y);

    gemm_mma<EPI_BIAS_GELU,1,true><<<g3072, 256, SMEMB>>>(y, w1r, w1r, w1r, b1, nullptr,
                                                          hb, hb, hb, Mrows, FFf, Ee);
    gemm_mma<EPI_BIAS_RES,1,false><<<g768, 256, SMEMB>>>(hb, w2r, w2r, w2r, b2, res,
                                                         out, out, out, Mrows, Ee, FFf);
}